// round 9
// baseline (speedup 1.0000x reference)
#include <cuda_runtime.h>
#include <cstdint>
#include <cstddef>

#define NB 8
#define NA 750000
#define PRE_NMS 4000
#define POST_NMS 1000
#define MIN_SIZE 0.001f
#define IMG_WF 1000.0f
#define IMG_HF 1000.0f
#define CAND_CAP 8192
#define BC_CAP 24576
#define SBUF 1024
#define WPR 64          /* mask words per row (63 used; word 63 never written -> 0) */
#define BBOX_CLIP 4.135166556742356f   /* log(1000/16) */
#define ROWS_A 1536     /* phase-A row limit = 24 chunks */
#define CHUNKS_A 24
#define C_HI 0.700007f
#define C_LO 0.699993f
#define M_HI 1.700007f
#define M_LO 1.699993f

typedef unsigned long long u64;

// ---------------- scratch (static device allocations; zero-initialized) ----
__device__ unsigned g_hist_c[NB * 1024];
__device__ unsigned g_hist_f[NB * 1024];
__device__ unsigned g_bucket_c[NB];
__device__ unsigned g_above_c[NB];
__device__ int      g_cand_cnt[NB];
__device__ int      g_bcnt[NB];
__device__ u64      g_cand[NB * CAND_CAP];
__device__ u64      g_bcand[NB * BC_CAP];
__device__ float4   g_box[NB * PRE_NMS];
__device__ float    g_prob[NB * PRE_NMS];
__device__ unsigned g_vmask32[NB * 128];
__device__ u64      g_mask[(size_t)NB * PRE_NMS * WPR];  // 16 MB
__device__ int      g_needB[NB];

// monotone key: larger float -> larger unsigned
__device__ __forceinline__ unsigned fkey(float f) {
    unsigned u = __float_as_uint(f);
    return u ^ ((u & 0x80000000u) ? 0xFFFFFFFFu : 0x80000000u);
}
__device__ __forceinline__ float unkey(unsigned k) {
    return __uint_as_float((k & 0x80000000u) ? (k ^ 0x80000000u) : ~k);
}

// ---------------- K0: zero small scratch ------------------------------------
__global__ void k_zero() {
    int t = blockIdx.x * blockDim.x + threadIdx.x;
    for (int i = t; i < NB * 1024; i += gridDim.x * blockDim.x) {
        g_hist_c[i] = 0u;
        g_hist_f[i] = 0u;
    }
    if (t < NB) { g_cand_cnt[t] = 0; g_bcnt[t] = 0; }
}

// ---------------- K1: coarse 10-bit histogram (float4, 2x unroll) -----------
__global__ void k_hist_c(const float* __restrict__ obj) {
    __shared__ unsigned h[1024];
    for (int t = threadIdx.x; t < 1024; t += blockDim.x) h[t] = 0u;
    __syncthreads();
    int img = blockIdx.y;
    const float4* o = (const float4*)(obj + (size_t)img * NA);
    int stride = gridDim.x * blockDim.x;
    int i = blockIdx.x * blockDim.x + threadIdx.x;
    for (; i + stride < NA / 4; i += 2 * stride) {
        float4 v0 = o[i];
        float4 v1 = o[i + stride];
        atomicAdd(&h[fkey(v0.x) >> 22], 1u);
        atomicAdd(&h[fkey(v0.y) >> 22], 1u);
        atomicAdd(&h[fkey(v0.z) >> 22], 1u);
        atomicAdd(&h[fkey(v0.w) >> 22], 1u);
        atomicAdd(&h[fkey(v1.x) >> 22], 1u);
        atomicAdd(&h[fkey(v1.y) >> 22], 1u);
        atomicAdd(&h[fkey(v1.z) >> 22], 1u);
        atomicAdd(&h[fkey(v1.w) >> 22], 1u);
    }
    if (i < NA / 4) {
        float4 v = o[i];
        atomicAdd(&h[fkey(v.x) >> 22], 1u);
        atomicAdd(&h[fkey(v.y) >> 22], 1u);
        atomicAdd(&h[fkey(v.z) >> 22], 1u);
        atomicAdd(&h[fkey(v.w) >> 22], 1u);
    }
    __syncthreads();
    for (int t = threadIdx.x; t < 1024; t += blockDim.x)
        if (h[t]) atomicAdd(&g_hist_c[img * 1024 + t], h[t]);
}

// ---------------- K2: pick coarse boundary bucket (1 warp/image) ------------
__global__ void k_select_c() {
    int img = blockIdx.x, lane = threadIdx.x;
    const unsigned* H = g_hist_c + img * 1024;
    unsigned part = 0;
    for (int r = lane * 32; r < lane * 32 + 32; r++) part += H[1023 - r];
    unsigned inc = part;
    for (int off = 1; off < 32; off <<= 1) {
        unsigned v = __shfl_up_sync(0xffffffffu, inc, off);
        if (lane >= off) inc += v;
    }
    unsigned needed = (unsigned)PRE_NMS;
    unsigned excl = inc - part;
    if (inc >= needed && excl < needed) {
        unsigned acc = excl;
        for (int r = lane * 32; r < lane * 32 + 32; r++) {
            unsigned hv = H[1023 - r];
            if (acc + hv >= needed) {
                g_bucket_c[img] = (unsigned)(1023 - r);
                g_above_c[img]  = acc;
                break;
            }
            acc += hv;
        }
    }
}

// ---------------- K3: fine histogram + collect (block-staged) ---------------
__global__ void k_hist_f(const float* __restrict__ obj) {
    __shared__ unsigned h[1024];
    __shared__ u64 su[SBUF], sb[SBUF];
    __shared__ int scu, scb, gu, gb;
    for (int t = threadIdx.x; t < 1024; t += blockDim.x) h[t] = 0u;
    if (threadIdx.x == 0) { scu = 0; scb = 0; }
    __syncthreads();
    int img = blockIdx.y;
    unsigned c = g_bucket_c[img];
    const float4* o = (const float4*)(obj + (size_t)img * NA);
    int stride = gridDim.x * blockDim.x;
    for (int i = blockIdx.x * blockDim.x + threadIdx.x; i < NA / 4; i += stride) {
        float4 v = o[i];
        unsigned k0 = fkey(v.x), k1 = fkey(v.y), k2 = fkey(v.z), k3 = fkey(v.w);
        unsigned mx = max(max(k0, k1), max(k2, k3));
        if ((mx >> 22) < c) continue;          // fast path: ~92% of iterations
#pragma unroll
        for (int j = 0; j < 4; j++) {
            unsigned key = (j == 0) ? k0 : (j == 1) ? k1 : (j == 2) ? k2 : k3;
            unsigned cb = key >> 22;
            if (cb < c) continue;
            u64 e = ((u64)key << 32) | (unsigned)(~(unsigned)(4 * i + j));
            if (cb > c) {
                int p = atomicAdd(&scu, 1);
                if (p < SBUF) su[p] = e;
                else {
                    int q = atomicAdd(&g_cand_cnt[img], 1);
                    if (q < CAND_CAP) g_cand[img * CAND_CAP + q] = e;
                }
            } else {
                atomicAdd(&h[(key >> 12) & 1023u], 1u);
                int p = atomicAdd(&scb, 1);
                if (p < SBUF) sb[p] = e;
                else {
                    int q = atomicAdd(&g_bcnt[img], 1);
                    if (q < BC_CAP) g_bcand[img * BC_CAP + q] = e;
                }
            }
        }
    }
    __syncthreads();
    if (threadIdx.x == 0) {
        int a = scu < SBUF ? scu : SBUF;
        gu = atomicAdd(&g_cand_cnt[img], a);
        int b2 = scb < SBUF ? scb : SBUF;
        gb = atomicAdd(&g_bcnt[img], b2);
    }
    __syncthreads();
    int nu = scu < SBUF ? scu : SBUF;
    for (int p = threadIdx.x; p < nu; p += blockDim.x) {
        int q = gu + p;
        if (q < CAND_CAP) g_cand[img * CAND_CAP + q] = su[p];
    }
    int nb = scb < SBUF ? scb : SBUF;
    for (int p = threadIdx.x; p < nb; p += blockDim.x) {
        int q = gb + p;
        if (q < BC_CAP) g_bcand[img * BC_CAP + q] = sb[p];
    }
    for (int t = threadIdx.x; t < 1024; t += blockDim.x)
        if (h[t]) atomicAdd(&g_hist_f[img * 1024 + t], h[t]);
}

// ---------------- K4: fine select + boundary filter (fused) -----------------
__global__ void k_select_f_compact() {
    int img = blockIdx.x;
    int lane = threadIdx.x & 31;
    __shared__ unsigned sT;
    if (threadIdx.x < 32) {               // warp 0: pick fine bucket
        const unsigned* H = g_hist_f + img * 1024;
        unsigned part = 0;
        for (int r = lane * 32; r < lane * 32 + 32; r++) part += H[1023 - r];
        unsigned inc = part;
        for (int off = 1; off < 32; off <<= 1) {
            unsigned v = __shfl_up_sync(0xffffffffu, inc, off);
            if (lane >= off) inc += v;
        }
        unsigned base   = g_above_c[img];
        unsigned needed = (unsigned)PRE_NMS - base;
        unsigned excl = inc - part;
        if (inc >= needed && excl < needed) {
            unsigned acc = excl;
            for (int r = lane * 32; r < lane * 32 + 32; r++) {
                unsigned hv = H[1023 - r];
                if (acc + hv >= needed) {
                    sT = (g_bucket_c[img] << 10) | (unsigned)(1023 - r);
                    break;
                }
                acc += hv;
            }
        }
    }
    __syncthreads();
    unsigned T = sT;
    int cnt = g_bcnt[img]; if (cnt > BC_CAP) cnt = BC_CAP;
    int nIter = (cnt + blockDim.x - 1) / blockDim.x;
    for (int it = 0; it < nIter; it++) {
        int i = it * blockDim.x + threadIdx.x;
        bool take = false;
        u64 e = 0ull;
        if (i < cnt) {
            e = g_bcand[img * BC_CAP + i];
            take = ((unsigned)(e >> 44) >= T);
        }
        unsigned m = __ballot_sync(0xffffffffu, take);
        if (m) {
            int ldr = __ffs(m) - 1;
            int base = 0;
            if (lane == ldr) base = atomicAdd(&g_cand_cnt[img], __popc(m));
            base = __shfl_sync(0xffffffffu, base, ldr);
            if (take) {
                int p = base + __popc(m & ((1u << lane) - 1u));
                if (p < CAND_CAP) g_cand[img * CAND_CAP + p] = e;
            }
        }
    }
}

// ---------------- K5: bitonic sort + decode + clip + sigmoid (fused) --------
__global__ void __launch_bounds__(1024, 1)
k_sortdecode(const float* __restrict__ deltas,
             const float* __restrict__ anchors) {
    extern __shared__ u64 s[];
    int img = blockIdx.x;
    int cnt = g_cand_cnt[img];
    if (cnt > CAND_CAP) cnt = CAND_CAP;
    unsigned S = (cnt <= 4096) ? 4096u : (unsigned)CAND_CAP;
    for (unsigned t = threadIdx.x; t < S; t += blockDim.x)
        s[t] = (t < (unsigned)cnt) ? g_cand[img * CAND_CAP + t] : 0ull;
    __syncthreads();
    for (unsigned k = 2; k <= S; k <<= 1) {
        for (unsigned j = k >> 1; j > 0; j >>= 1) {
            for (unsigned idx = threadIdx.x; idx < S; idx += blockDim.x) {
                unsigned ixj = idx ^ j;
                if (ixj > idx) {
                    u64 a = s[idx], b = s[ixj];
                    bool blk = ((idx & k) == 0u);     // descending overall
                    if (blk ? (a < b) : (a > b)) { s[idx] = b; s[ixj] = a; }
                }
            }
            __syncthreads();
        }
    }
    // decode top-4000 directly from sorted smem
    for (int t = threadIdx.x; t < 4096; t += blockDim.x) {
        bool inr = (t < PRE_NMS);
        u64 key = inr ? s[t] : 0ull;
        int idx = inr ? (int)(~(unsigned)key) : 0;
        float4 a = ((const float4*)anchors)[idx];
        float4 d = ((const float4*)deltas)[(size_t)img * NA + idx];
        float w = a.z - a.x, h = a.w - a.y;
        float cx = a.x + 0.5f * w, cy = a.y + 0.5f * h;
        float dw = fminf(d.z, BBOX_CLIP), dh = fminf(d.w, BBOX_CLIP);
        float pcx = d.x * w + cx, pcy = d.y * h + cy;
        float pw = expf(dw) * w, ph = expf(dh) * h;
        float x1 = pcx - 0.5f * pw, y1 = pcy - 0.5f * ph;
        float x2 = pcx + 0.5f * pw, y2 = pcy + 0.5f * ph;
        x1 = fminf(fmaxf(x1, 0.f), IMG_WF);
        y1 = fminf(fmaxf(y1, 0.f), IMG_HF);
        x2 = fminf(fmaxf(x2, 0.f), IMG_WF);
        y2 = fminf(fmaxf(y2, 0.f), IMG_HF);
        bool validb = false;
        if (inr) {
            g_box[img * PRE_NMS + t] = make_float4(x1, y1, x2, y2);
            validb = ((x2 - x1) >= MIN_SIZE) && ((y2 - y1) >= MIN_SIZE);
            float sc = unkey((unsigned)(key >> 32));
            g_prob[img * PRE_NMS + t] = 1.f / (1.f + expf(-sc));
        }
        unsigned bb = __ballot_sync(0xffffffffu, validb);
        if ((threadIdx.x & 31) == 0 && inr)
            g_vmask32[img * 128 + (t >> 5)] = bb;
    }
}

// ---------------- K6: IoU suppression bitmask (phased, shaved loop) ---------
// sup: inter > c*(ra+car-inter)  <=>  (1+c)*inter - c*ra > c*car
__global__ void k_iou(int rb_base, int check_flag) {
    int img = blockIdx.z, rb = blockIdx.y + rb_base, cb = blockIdx.x;
    if (check_flag && !g_needB[img]) return;
    if (cb * 64 + 64 <= rb * 128) return;  // entire col-block below diagonal
    __shared__ float4 cbox[64];
    __shared__ float2 csc[64];
    int col0 = cb * 64;
    if (threadIdx.x < 64) {
        int c = col0 + threadIdx.x;
        float4 q = (c < PRE_NMS) ? g_box[img * PRE_NMS + c] : make_float4(0, 0, 0, 0);
        cbox[threadIdx.x] = q;
        float car = (q.z - q.x) * (q.w - q.y);
        csc[threadIdx.x] = make_float2(C_HI * car, C_LO * car);
    }
    __syncthreads();
    int row = rb * 128 + threadIdx.x;
    if (row >= PRE_NMS) return;
    if (col0 + 63 <= row) return;          // this row's word all below/equal diag
    float4 r = g_box[img * PRE_NMS + row];
    float ra = (r.z - r.x) * (r.w - r.y);
    float nra_hi = -C_HI * ra;
    float nra_lo = -C_LO * ra;
    unsigned mlo = 0u, mhi = 0u, blo = 0u, bhi = 0u;
#pragma unroll 16
    for (int j = 0; j < 64; j++) {
        float4 b = cbox[j];
        float2 sc = csc[j];
        float xx1 = fmaxf(r.x, b.x), yy1 = fmaxf(r.y, b.y);
        float xx2 = fminf(r.z, b.z), yy2 = fminf(r.w, b.w);
        float ww = fmaxf(xx2 - xx1, 0.f), hh = fmaxf(yy2 - yy1, 0.f);
        float inter = ww * hh;
        bool sup  = __fmaf_rn(M_HI, inter, nra_hi) > sc.x;
        bool geq  = __fmaf_rn(M_LO, inter, nra_lo) >= sc.y;
        unsigned bit = 1u << (j & 31);
        if (j < 32) { mlo |= sup ? bit : 0u; blo |= geq ? bit : 0u; }
        else        { mhi |= sup ? bit : 0u; bhi |= geq ? bit : 0u; }
    }
    u64 msup  = ((u64)mhi << 32) | mlo;
    u64 mband = (((u64)bhi << 32) | blo) & ~msup;
    int rel = row - col0;                  // keep only cols strictly above diag
    if (rel >= 0) {
        u64 hi = (rel >= 63) ? 0ull : (~0ull << (rel + 1));
        msup &= hi;
        mband &= hi;
    }
    while (mband) {                        // rare: bit-exact reference decision
        int j = __ffsll((long long)mband) - 1;
        mband &= mband - 1;
        float4 b = cbox[j];
        float carj = (b.z - b.x) * (b.w - b.y);
        float xx1 = fmaxf(r.x, b.x), yy1 = fmaxf(r.y, b.y);
        float xx2 = fminf(r.z, b.z), yy2 = fminf(r.w, b.w);
        float ww = fmaxf(xx2 - xx1, 0.f), hh = fmaxf(yy2 - yy1, 0.f);
        float inter = ww * hh;
        float uni = (ra + carj) - inter;
        if ((inter / fmaxf(uni, 1e-9f)) > 0.7f) msup |= (1ull << j);
    }
    g_mask[((size_t)img * PRE_NMS + row) * WPR + cb] = msup;
}

// ---------------- K6.5: prescan first 24 chunks; set need-phase-B flag ------
__global__ void k_prescan() {
    int img = blockIdx.x, lane = threadIdx.x;
    __shared__ u64 diag_sh[64];
    const unsigned* vm = g_vmask32 + img * 128;
    u64 r0 = ~((u64)vm[2 * lane] | ((u64)vm[2 * lane + 1] << 32));
    u64 r1 = ~((u64)vm[64 + 2 * lane] | ((u64)vm[65 + 2 * lane] << 32));
    const u64* M = g_mask + (size_t)img * PRE_NMS * WPR;
    u64 nd0 = M[(size_t)(2 * lane) * WPR + 0];
    u64 nd1 = M[(size_t)(2 * lane + 1) * WPR + 0];
    int n = 0;
    for (int ch = 0; ch < CHUNKS_A; ch++) {
        diag_sh[2 * lane] = nd0;
        diag_sh[2 * lane + 1] = nd1;
        __syncwarp();
        if (ch < CHUNKS_A - 1) {
            int base = (ch + 1) * 64;
            nd0 = M[(size_t)(base + 2 * lane) * WPR + (ch + 1)];
            nd1 = M[(size_t)(base + 2 * lane + 1) * WPR + (ch + 1)];
        }
        u64 remw = (ch < 32) ? __shfl_sync(0xffffffffu, r0, ch)
                             : __shfl_sync(0xffffffffu, r1, ch - 32);
        u64 km = 0ull;
#pragma unroll
        for (int b = 0; b < 64; b += 2) {
            u64 d0 = diag_sh[b], d1 = diag_sh[b + 1];
            u64 d01 = d0 | d1;
            u64 c01 = remw | d1;
            u64 c10 = remw | d0;
            u64 c11 = remw | d01;
            bool k0  = (remw & (1ull << b)) == 0ull;
            bool k1k = (c10  & (1ull << (b + 1))) == 0ull;
            bool k1s = (remw & (1ull << (b + 1))) == 0ull;
            u64 lo  = k0 ? c10 : remw;
            u64 hi2 = k0 ? c11 : c01;
            bool k1 = k0 ? k1k : k1s;
            remw = k1 ? hi2 : lo;
            km |= (k0 ? (1ull << b) : 0ull) | (k1 ? (1ull << (b + 1)) : 0ull);
        }
        n += __popcll(km);
        if (n >= POST_NMS) break;
        u64 t = km;
        while (t) {
            int rr[8];
#pragma unroll
            for (int u = 0; u < 8; u++) {
                if (t) { rr[u] = ch * 64 + (__ffsll((long long)t) - 1); t &= t - 1; }
                else    rr[u] = -1;
            }
            u64 pa[8], pb[8];
#pragma unroll
            for (int u = 0; u < 8; u++) {
                if (rr[u] >= 0) {
                    const u64* rp = M + (size_t)rr[u] * WPR;
                    pa[u] = rp[lane];
                    pb[u] = rp[32 + lane];
                } else { pa[u] = 0ull; pb[u] = 0ull; }
            }
#pragma unroll
            for (int u = 0; u < 8; u++) { r0 |= pa[u]; r1 |= pb[u]; }
        }
        __syncwarp();
    }
    if (lane == 0) g_needB[img] = (n < POST_NMS) ? 1 : 0;
}

// ---------------- K7: greedy NMS (2-bit speculative) + output (fused) -------
// 256 threads: keeps warp-0's fat register state under the per-block budget.
// layout: [proposals (8,1000,4) f32][scores (8,1000) f32]
__global__ void __launch_bounds__(256)
k_nmsout(float* __restrict__ out) {
    int img = blockIdx.x;
    __shared__ u64 diag_sh[64];
    __shared__ u64 s_km[63];
    __shared__ int s_kept[POST_NMS];
    __shared__ int s_n;
    __shared__ unsigned sh[256];
    int tid = threadIdx.x;

    if (tid < 32) {                        // warp 0: sequential greedy scan
        int lane = tid;
        const unsigned* vm = g_vmask32 + img * 128;
        u64 r0 = ~((u64)vm[2 * lane] | ((u64)vm[2 * lane + 1] << 32));
        u64 r1 = ~((u64)vm[64 + 2 * lane] | ((u64)vm[65 + 2 * lane] << 32));
        const u64* M = g_mask + (size_t)img * PRE_NMS * WPR;
        u64 nd0 = M[(size_t)(2 * lane) * WPR + 0];
        u64 nd1 = M[(size_t)(2 * lane + 1) * WPR + 0];
        int n = 0;
        for (int ch = 0; ch < 63; ch++) {
            diag_sh[2 * lane] = nd0;
            diag_sh[2 * lane + 1] = nd1;
            __syncwarp();
            if (ch < 62) {
                int base = (ch + 1) * 64;
                int ra2 = base + 2 * lane, rb2 = ra2 + 1;
                nd0 = (ra2 < PRE_NMS) ? M[(size_t)ra2 * WPR + (ch + 1)] : 0ull;
                nd1 = (rb2 < PRE_NMS) ? M[(size_t)rb2 * WPR + (ch + 1)] : 0ull;
            }
            u64 remw = (ch < 32) ? __shfl_sync(0xffffffffu, r0, ch)
                                 : __shfl_sync(0xffffffffu, r1, ch - 32);
            u64 km = 0ull;
#pragma unroll
            for (int b = 0; b < 64; b += 2) {
                u64 d0 = diag_sh[b], d1 = diag_sh[b + 1];
                u64 d01 = d0 | d1;                 // off-chain
                u64 c01 = remw | d1;
                u64 c10 = remw | d0;
                u64 c11 = remw | d01;
                bool k0  = (remw & (1ull << b)) == 0ull;
                bool k1k = (c10  & (1ull << (b + 1))) == 0ull;
                bool k1s = (remw & (1ull << (b + 1))) == 0ull;
                u64 lo  = k0 ? c10 : remw;
                u64 hi2 = k0 ? c11 : c01;
                bool k1 = k0 ? k1k : k1s;
                remw = k1 ? hi2 : lo;
                km |= (k0 ? (1ull << b) : 0ull) | (k1 ? (1ull << (b + 1)) : 0ull);
            }
            // parallel kept-list extraction (rank by popcount)
            {
                bool kb0 = (km >> lane) & 1ull;
                int rk0 = __popcll(km & ((1ull << lane) - 1ull));
                int slot0 = n + rk0;
                if (kb0 && slot0 < POST_NMS) s_kept[slot0] = ch * 64 + lane;
                int l2 = lane + 32;
                bool kb1 = (km >> l2) & 1ull;
                int rk1 = __popcll(km & ((1ull << l2) - 1ull));
                int slot1 = n + rk1;
                if (kb1 && slot1 < POST_NMS) s_kept[slot1] = ch * 64 + l2;
            }
            if (lane == 0) s_km[ch] = km;
            n += __popcll(km);
            if (n >= POST_NMS) break;
            // OR kept rows' full masks into remv, 8-wide batches for MLP
            u64 t = km;
            while (t) {
                int rr[8];
#pragma unroll
                for (int u = 0; u < 8; u++) {
                    if (t) { rr[u] = ch * 64 + (__ffsll((long long)t) - 1); t &= t - 1; }
                    else    rr[u] = -1;
                }
                u64 pa[8], pb[8];
#pragma unroll
                for (int u = 0; u < 8; u++) {
                    if (rr[u] >= 0) {
                        const u64* rp = M + (size_t)rr[u] * WPR;
                        pa[u] = rp[lane];
                        pb[u] = rp[32 + lane];   // word 63 never written -> 0
                    } else { pa[u] = 0ull; pb[u] = 0ull; }
                }
#pragma unroll
                for (int u = 0; u < 8; u++) { r0 |= pa[u]; r1 |= pb[u]; }
            }
            __syncwarp();
        }
        if (lane == 0) s_n = n;
    }
    __syncthreads();

    // ---- output assembly (256 threads) ----
    int n = s_n;
    int lim = n < POST_NMS ? n : POST_NMS;
    for (int s2 = tid; s2 < lim; s2 += 256) {
        int i = s_kept[s2];
        ((float4*)out)[img * POST_NMS + s2] = g_box[img * PRE_NMS + i];
        out[NB * POST_NMS * 4 + img * POST_NMS + s2] = g_prob[img * PRE_NMS + i];
    }
    if (n >= POST_NMS) return;
    // fill with non-kept indices ascending, score = -inf (top_k tie rule)
    unsigned base = 0;
    for (int chunk = 0; chunk < PRE_NMS; chunk += 256) {
        int i = chunk + tid;
        unsigned f = 0u;
        if (i < PRE_NMS) {
            u64 kw = s_km[i >> 6];
            f = ((kw >> (i & 63)) & 1ull) ? 0u : 1u;
        }
        sh[tid] = f;
        __syncthreads();
        for (int off = 1; off < 256; off <<= 1) {
            unsigned vv = (tid >= off) ? sh[tid - off] : 0u;
            __syncthreads();
            sh[tid] += vv;
            __syncthreads();
        }
        unsigned excl = sh[tid] - f;
        int slot = n + (int)(base + excl);
        if (f && slot < POST_NMS) {
            ((float4*)out)[img * POST_NMS + slot] = g_box[img * PRE_NMS + i];
            out[NB * POST_NMS * 4 + img * POST_NMS + slot] =
                __int_as_float(0xff800000);  // -inf
        }
        base += sh[255];
        __syncthreads();
    }
}

// ---------------- host ------------------------------------------------------
extern "C" void kernel_launch(void* const* d_in, const int* in_sizes, int n_in,
                              void* d_out, int out_size) {
    const float* obj     = (const float*)d_in[0];   // (8, 750000)
    const float* deltas  = (const float*)d_in[1];   // (8, 750000, 4)
    const float* anchors = (const float*)d_in[2];   // (750000, 4)
    float* out = (float*)d_out;

    k_zero<<<8, 1024>>>();
    k_hist_c<<<dim3(144, NB), 256>>>(obj);
    k_select_c<<<NB, 32>>>();
    k_hist_f<<<dim3(144, NB), 256>>>(obj);
    k_select_f_compact<<<NB, 256>>>();

    cudaFuncSetAttribute(k_sortdecode, cudaFuncAttributeMaxDynamicSharedMemorySize,
                         CAND_CAP * (int)sizeof(u64));
    k_sortdecode<<<NB, 1024, CAND_CAP * sizeof(u64)>>>(deltas, anchors);

    k_iou<<<dim3(63, 12, NB), 128>>>(0, 0);    // phase A: rows < 1536
    k_prescan<<<NB, 32>>>();
    k_iou<<<dim3(63, 20, NB), 128>>>(12, 1);   // phase B: rows >= 1536, if needed
    k_nmsout<<<NB, 256>>>(out);
}

// round 10
// speedup vs baseline: 1.0242x; 1.0242x over previous
#include <cuda_runtime.h>
#include <cstdint>
#include <cstddef>

#define NB 8
#define NA 750000
#define PRE_NMS 4000
#define POST_NMS 1000
#define MIN_SIZE 0.001f
#define IMG_WF 1000.0f
#define IMG_HF 1000.0f
#define CAND_CAP 8192
#define BC_CAP 24576
#define SBUF 1024
#define WPR 64          /* mask words per row (63 used; word 63 never set -> 0) */
#define BBOX_CLIP 4.135166556742356f   /* log(1000/16) */
#define NTILE 63        /* 63 tiles x 64 = 4032 slots, 4000 used */
#define PBOX_STRIDE 4032
#define C_HI 0.700007f
#define C_LO 0.699993f

typedef unsigned long long u64;

// ---------------- scratch (static device allocations; zero-initialized) ----
__device__ unsigned g_hist_c[NB * 1024];
__device__ unsigned g_hist_f[NB * 1024];
__device__ unsigned g_bucket_c[NB];
__device__ unsigned g_above_c[NB];
__device__ int      g_cand_cnt[NB];
__device__ int      g_bcnt[NB];
__device__ u64      g_cand[NB * CAND_CAP];
__device__ u64      g_bcand[NB * BC_CAP];
__device__ float4   g_box[NB * PRE_NMS];
__device__ float    g_prob[NB * PRE_NMS];
__device__ unsigned g_vmask32[NB * 128];
__device__ u64      g_mask[(size_t)NB * PRE_NMS * WPR];  // 16 MB, re-zeroed per run
__device__ float4   g_pbox[NB * PBOX_STRIDE];
__device__ int      g_prank[NB * PBOX_STRIDE];
__device__ float4   g_hull[NB * NTILE];
__device__ float2   g_harea[NB * NTILE];

// monotone key: larger float -> larger unsigned
__device__ __forceinline__ unsigned fkey(float f) {
    unsigned u = __float_as_uint(f);
    return u ^ ((u & 0x80000000u) ? 0xFFFFFFFFu : 0x80000000u);
}
__device__ __forceinline__ float unkey(unsigned k) {
    return __uint_as_float((k & 0x80000000u) ? (k ^ 0x80000000u) : ~k);
}

// ---------------- K0: zero mask + small scratch -----------------------------
__global__ void k_zero() {
    size_t t = (size_t)blockIdx.x * blockDim.x + threadIdx.x;
    size_t stride = (size_t)gridDim.x * blockDim.x;
    ulonglong2* m = (ulonglong2*)g_mask;
    size_t nm = sizeof(g_mask) / 16;
    for (size_t i = t; i < nm; i += stride) m[i] = make_ulonglong2(0ull, 0ull);
    if (t < NB * 1024) { g_hist_c[t] = 0u; g_hist_f[t] = 0u; }
    if (t < NB) { g_cand_cnt[t] = 0; g_bcnt[t] = 0; }
}

// ---------------- K1: coarse 10-bit histogram (float4, 2x unroll) -----------
__global__ void k_hist_c(const float* __restrict__ obj) {
    __shared__ unsigned h[1024];
    for (int t = threadIdx.x; t < 1024; t += blockDim.x) h[t] = 0u;
    __syncthreads();
    int img = blockIdx.y;
    const float4* o = (const float4*)(obj + (size_t)img * NA);
    int stride = gridDim.x * blockDim.x;
    int i = blockIdx.x * blockDim.x + threadIdx.x;
    for (; i + stride < NA / 4; i += 2 * stride) {
        float4 v0 = o[i];
        float4 v1 = o[i + stride];
        atomicAdd(&h[fkey(v0.x) >> 22], 1u);
        atomicAdd(&h[fkey(v0.y) >> 22], 1u);
        atomicAdd(&h[fkey(v0.z) >> 22], 1u);
        atomicAdd(&h[fkey(v0.w) >> 22], 1u);
        atomicAdd(&h[fkey(v1.x) >> 22], 1u);
        atomicAdd(&h[fkey(v1.y) >> 22], 1u);
        atomicAdd(&h[fkey(v1.z) >> 22], 1u);
        atomicAdd(&h[fkey(v1.w) >> 22], 1u);
    }
    if (i < NA / 4) {
        float4 v = o[i];
        atomicAdd(&h[fkey(v.x) >> 22], 1u);
        atomicAdd(&h[fkey(v.y) >> 22], 1u);
        atomicAdd(&h[fkey(v.z) >> 22], 1u);
        atomicAdd(&h[fkey(v.w) >> 22], 1u);
    }
    __syncthreads();
    for (int t = threadIdx.x; t < 1024; t += blockDim.x)
        if (h[t]) atomicAdd(&g_hist_c[img * 1024 + t], h[t]);
}

// ---------------- K2: pick coarse boundary bucket (1 warp/image) ------------
__global__ void k_select_c() {
    int img = blockIdx.x, lane = threadIdx.x;
    const unsigned* H = g_hist_c + img * 1024;
    unsigned part = 0;
    for (int r = lane * 32; r < lane * 32 + 32; r++) part += H[1023 - r];
    unsigned inc = part;
    for (int off = 1; off < 32; off <<= 1) {
        unsigned v = __shfl_up_sync(0xffffffffu, inc, off);
        if (lane >= off) inc += v;
    }
    unsigned needed = (unsigned)PRE_NMS;
    unsigned excl = inc - part;
    if (inc >= needed && excl < needed) {
        unsigned acc = excl;
        for (int r = lane * 32; r < lane * 32 + 32; r++) {
            unsigned hv = H[1023 - r];
            if (acc + hv >= needed) {
                g_bucket_c[img] = (unsigned)(1023 - r);
                g_above_c[img]  = acc;
                break;
            }
            acc += hv;
        }
    }
}

// ---------------- K3: fine histogram + collect (block-staged) ---------------
__global__ void k_hist_f(const float* __restrict__ obj) {
    __shared__ unsigned h[1024];
    __shared__ u64 su[SBUF], sb[SBUF];
    __shared__ int scu, scb, gu, gb;
    for (int t = threadIdx.x; t < 1024; t += blockDim.x) h[t] = 0u;
    if (threadIdx.x == 0) { scu = 0; scb = 0; }
    __syncthreads();
    int img = blockIdx.y;
    unsigned c = g_bucket_c[img];
    const float4* o = (const float4*)(obj + (size_t)img * NA);
    int stride = gridDim.x * blockDim.x;
    for (int i = blockIdx.x * blockDim.x + threadIdx.x; i < NA / 4; i += stride) {
        float4 v = o[i];
        unsigned k0 = fkey(v.x), k1 = fkey(v.y), k2 = fkey(v.z), k3 = fkey(v.w);
        unsigned mx = max(max(k0, k1), max(k2, k3));
        if ((mx >> 22) < c) continue;          // fast path: ~92% of iterations
#pragma unroll
        for (int j = 0; j < 4; j++) {
            unsigned key = (j == 0) ? k0 : (j == 1) ? k1 : (j == 2) ? k2 : k3;
            unsigned cb = key >> 22;
            if (cb < c) continue;
            u64 e = ((u64)key << 32) | (unsigned)(~(unsigned)(4 * i + j));
            if (cb > c) {
                int p = atomicAdd(&scu, 1);
                if (p < SBUF) su[p] = e;
                else {
                    int q = atomicAdd(&g_cand_cnt[img], 1);
                    if (q < CAND_CAP) g_cand[img * CAND_CAP + q] = e;
                }
            } else {
                atomicAdd(&h[(key >> 12) & 1023u], 1u);
                int p = atomicAdd(&scb, 1);
                if (p < SBUF) sb[p] = e;
                else {
                    int q = atomicAdd(&g_bcnt[img], 1);
                    if (q < BC_CAP) g_bcand[img * BC_CAP + q] = e;
                }
            }
        }
    }
    __syncthreads();
    if (threadIdx.x == 0) {
        int a = scu < SBUF ? scu : SBUF;
        gu = atomicAdd(&g_cand_cnt[img], a);
        int b2 = scb < SBUF ? scb : SBUF;
        gb = atomicAdd(&g_bcnt[img], b2);
    }
    __syncthreads();
    int nu = scu < SBUF ? scu : SBUF;
    for (int p = threadIdx.x; p < nu; p += blockDim.x) {
        int q = gu + p;
        if (q < CAND_CAP) g_cand[img * CAND_CAP + q] = su[p];
    }
    int nb = scb < SBUF ? scb : SBUF;
    for (int p = threadIdx.x; p < nb; p += blockDim.x) {
        int q = gb + p;
        if (q < BC_CAP) g_bcand[img * BC_CAP + q] = sb[p];
    }
    for (int t = threadIdx.x; t < 1024; t += blockDim.x)
        if (h[t]) atomicAdd(&g_hist_f[img * 1024 + t], h[t]);
}

// ---------------- K4: fine select + boundary filter (fused) -----------------
__global__ void k_select_f_compact() {
    int img = blockIdx.x;
    int lane = threadIdx.x & 31;
    __shared__ unsigned sT;
    if (threadIdx.x < 32) {               // warp 0: pick fine bucket
        const unsigned* H = g_hist_f + img * 1024;
        unsigned part = 0;
        for (int r = lane * 32; r < lane * 32 + 32; r++) part += H[1023 - r];
        unsigned inc = part;
        for (int off = 1; off < 32; off <<= 1) {
            unsigned v = __shfl_up_sync(0xffffffffu, inc, off);
            if (lane >= off) inc += v;
        }
        unsigned base   = g_above_c[img];
        unsigned needed = (unsigned)PRE_NMS - base;
        unsigned excl = inc - part;
        if (inc >= needed && excl < needed) {
            unsigned acc = excl;
            for (int r = lane * 32; r < lane * 32 + 32; r++) {
                unsigned hv = H[1023 - r];
                if (acc + hv >= needed) {
                    sT = (g_bucket_c[img] << 10) | (unsigned)(1023 - r);
                    break;
                }
                acc += hv;
            }
        }
    }
    __syncthreads();
    unsigned T = sT;
    int cnt = g_bcnt[img]; if (cnt > BC_CAP) cnt = BC_CAP;
    int nIter = (cnt + blockDim.x - 1) / blockDim.x;
    for (int it = 0; it < nIter; it++) {
        int i = it * blockDim.x + threadIdx.x;
        bool take = false;
        u64 e = 0ull;
        if (i < cnt) {
            e = g_bcand[img * BC_CAP + i];
            take = ((unsigned)(e >> 44) >= T);
        }
        unsigned m = __ballot_sync(0xffffffffu, take);
        if (m) {
            int ldr = __ffs(m) - 1;
            int base = 0;
            if (lane == ldr) base = atomicAdd(&g_cand_cnt[img], __popc(m));
            base = __shfl_sync(0xffffffffu, base, ldr);
            if (take) {
                int p = base + __popc(m & ((1u << lane) - 1u));
                if (p < CAND_CAP) g_cand[img * CAND_CAP + p] = e;
            }
        }
    }
}

// ---------------- K5: bitonic sort + decode + clip + sigmoid (fused) --------
__global__ void __launch_bounds__(1024, 1)
k_sortdecode(const float* __restrict__ deltas,
             const float* __restrict__ anchors) {
    extern __shared__ u64 s[];
    int img = blockIdx.x;
    int cnt = g_cand_cnt[img];
    if (cnt > CAND_CAP) cnt = CAND_CAP;
    unsigned S = (cnt <= 4096) ? 4096u : (unsigned)CAND_CAP;
    for (unsigned t = threadIdx.x; t < S; t += blockDim.x)
        s[t] = (t < (unsigned)cnt) ? g_cand[img * CAND_CAP + t] : 0ull;
    __syncthreads();
    for (unsigned k = 2; k <= S; k <<= 1) {
        for (unsigned j = k >> 1; j > 0; j >>= 1) {
            for (unsigned idx = threadIdx.x; idx < S; idx += blockDim.x) {
                unsigned ixj = idx ^ j;
                if (ixj > idx) {
                    u64 a = s[idx], b = s[ixj];
                    bool blk = ((idx & k) == 0u);     // descending overall
                    if (blk ? (a < b) : (a > b)) { s[idx] = b; s[ixj] = a; }
                }
            }
            __syncthreads();
        }
    }
    // decode top-4000 directly from sorted smem
    for (int t = threadIdx.x; t < 4096; t += blockDim.x) {
        bool inr = (t < PRE_NMS);
        u64 key = inr ? s[t] : 0ull;
        int idx = inr ? (int)(~(unsigned)key) : 0;
        float4 a = ((const float4*)anchors)[idx];
        float4 d = ((const float4*)deltas)[(size_t)img * NA + idx];
        float w = a.z - a.x, h = a.w - a.y;
        float cx = a.x + 0.5f * w, cy = a.y + 0.5f * h;
        float dw = fminf(d.z, BBOX_CLIP), dh = fminf(d.w, BBOX_CLIP);
        float pcx = d.x * w + cx, pcy = d.y * h + cy;
        float pw = expf(dw) * w, ph = expf(dh) * h;
        float x1 = pcx - 0.5f * pw, y1 = pcy - 0.5f * ph;
        float x2 = pcx + 0.5f * pw, y2 = pcy + 0.5f * ph;
        x1 = fminf(fmaxf(x1, 0.f), IMG_WF);
        y1 = fminf(fmaxf(y1, 0.f), IMG_HF);
        x2 = fminf(fmaxf(x2, 0.f), IMG_WF);
        y2 = fminf(fmaxf(y2, 0.f), IMG_HF);
        bool validb = false;
        if (inr) {
            g_box[img * PRE_NMS + t] = make_float4(x1, y1, x2, y2);
            validb = ((x2 - x1) >= MIN_SIZE) && ((y2 - y1) >= MIN_SIZE);
            float sc = unkey((unsigned)(key >> 32));
            g_prob[img * PRE_NMS + t] = 1.f / (1.f + expf(-sc));
        }
        unsigned bb = __ballot_sync(0xffffffffu, validb);
        if ((threadIdx.x & 31) == 0 && inr)
            g_vmask32[img * 128 + (t >> 5)] = bb;
    }
}

// ---------------- K6: spatial bucketing permutation (counting sort) ---------
__device__ __forceinline__ int box_key(float4 b) {
    float cx = 0.5f * (b.x + b.z), cy = 0.5f * (b.y + b.w);
    float area = (b.z - b.x) * (b.w - b.y);
    int gx = min(7, max(0, (int)(cx * 0.008f)));
    int gy = min(7, max(0, (int)(cy * 0.008f)));
    int aexp = (int)((__float_as_uint(area) >> 23) & 0xff);
    int band = min(3, max(0, (aexp - 131) >> 2));
    return band * 64 + gy * 8 + gx;
}

__global__ void __launch_bounds__(256) k_perm() {
    int img = blockIdx.x, tid = threadIdx.x;
    __shared__ int hist[256], offs[256], cnt[256], scan[256];
    hist[tid] = 0; cnt[tid] = 0;
    __syncthreads();
    for (int i = tid; i < PRE_NMS; i += 256)
        atomicAdd(&hist[box_key(g_box[img * PRE_NMS + i])], 1);
    __syncthreads();
    scan[tid] = hist[tid];
    __syncthreads();
    for (int off = 1; off < 256; off <<= 1) {
        int v = (tid >= off) ? scan[tid - off] : 0;
        __syncthreads();
        scan[tid] += v;
        __syncthreads();
    }
    offs[tid] = scan[tid] - hist[tid];
    __syncthreads();
    for (int i = tid; i < PRE_NMS; i += 256) {
        float4 b = g_box[img * PRE_NMS + i];
        int key = box_key(b);
        int pos = offs[key] + atomicAdd(&cnt[key], 1);
        g_pbox[img * PBOX_STRIDE + pos] = b;
        g_prank[img * PBOX_STRIDE + pos] = i;
    }
    for (int i = PRE_NMS + tid; i < PBOX_STRIDE; i += 256) {
        g_pbox[img * PBOX_STRIDE + i] = make_float4(0.f, 0.f, 0.f, 0.f);
        g_prank[img * PBOX_STRIDE + i] = 0;
    }
}

// ---------------- K7: per-tile hulls + area bounds --------------------------
__global__ void __launch_bounds__(512) k_hull() {
    int img = blockIdx.x;
    int w = threadIdx.x >> 5, lane = threadIdx.x & 31;
    for (int t = w; t < NTILE; t += 16) {
        int n = (t == NTILE - 1) ? (PRE_NMS - (NTILE - 1) * 64) : 64;
        float mnx = 1e30f, mny = 1e30f, mxx = -1e30f, mxy = -1e30f;
        float mna = 1e30f, mxa = -1e30f;
        for (int j = lane; j < n; j += 32) {
            float4 b = g_pbox[img * PBOX_STRIDE + t * 64 + j];
            float a = (b.z - b.x) * (b.w - b.y);
            mnx = fminf(mnx, b.x); mny = fminf(mny, b.y);
            mxx = fmaxf(mxx, b.z); mxy = fmaxf(mxy, b.w);
            mna = fminf(mna, a);   mxa = fmaxf(mxa, a);
        }
        for (int o = 16; o; o >>= 1) {
            mnx = fminf(mnx, __shfl_down_sync(0xffffffffu, mnx, o));
            mny = fminf(mny, __shfl_down_sync(0xffffffffu, mny, o));
            mxx = fmaxf(mxx, __shfl_down_sync(0xffffffffu, mxx, o));
            mxy = fmaxf(mxy, __shfl_down_sync(0xffffffffu, mxy, o));
            mna = fminf(mna, __shfl_down_sync(0xffffffffu, mna, o));
            mxa = fmaxf(mxa, __shfl_down_sync(0xffffffffu, mxa, o));
        }
        if (lane == 0) {
            g_hull[img * NTILE + t]  = make_float4(mnx, mny, mxx, mxy);
            g_harea[img * NTILE + t] = make_float2(mna, mxa);
        }
    }
}

// ---------------- K8: sparse IoU via tile hull pruning ----------------------
// IoU>0.7 requires bbox overlap and area ratio in [0.7,1.43]; hull tests are
// conservative (padded), so skips are sound. Suppressed bits scattered to
// score-rank positions by atomicOr (commutative -> deterministic).
__global__ void __launch_bounds__(128) k_iou_sparse() {
    int img = blockIdx.y;
    int p = blockIdx.x * 128 + threadIdx.x;
    __shared__ float4 shull[NTILE];
    __shared__ float2 sharea[NTILE];
    for (int t = threadIdx.x; t < NTILE; t += 128) {
        shull[t]  = g_hull[img * NTILE + t];
        sharea[t] = g_harea[img * NTILE + t];
    }
    __syncthreads();
    if (p >= PRE_NMS) return;
    const float4* PB = g_pbox + img * PBOX_STRIDE;
    const int*    PR = g_prank + img * PBOX_STRIDE;
    float4 r = PB[p];
    float ra = (r.z - r.x) * (r.w - r.y);
    int myrank = PR[p];
    u64* Mimg = g_mask + (size_t)img * PRE_NMS * WPR;
    int t0 = p >> 6;
    for (int t = t0; t < NTILE; t++) {
        float4 hl = shull[t];
        float2 ab = sharea[t];
        bool pass = (r.x <= hl.z) && (hl.x <= r.z) &&
                    (r.y <= hl.w) && (hl.y <= r.w) &&
                    (ra >= 0.65f * ab.x) && (ra <= 1.53847f * ab.y);
        if (!pass) continue;
        int jstart = (t == t0) ? (p & 63) + 1 : 0;
        int jend = (t == NTILE - 1) ? (PRE_NMS - (NTILE - 1) * 64) : 64;
        if (jstart >= jend) continue;
        u64 msup = 0ull, mband = 0ull;
        for (int j = jstart; j < jend; j++) {
            float4 b = PB[t * 64 + j];
            float xx1 = fmaxf(r.x, b.x), yy1 = fmaxf(r.y, b.y);
            float xx2 = fminf(r.z, b.z), yy2 = fminf(r.w, b.w);
            float ww = fmaxf(xx2 - xx1, 0.f), hh = fmaxf(yy2 - yy1, 0.f);
            float inter = ww * hh;
            float car = (b.z - b.x) * (b.w - b.y);
            float uni = (ra + car) - inter;
            bool sup = __fmaf_rn(-C_HI, uni, inter) > 0.f;
            bool geq = __fmaf_rn(-C_LO, uni, inter) >= 0.f;
            msup  |= sup ? (1ull << j) : 0ull;
            mband |= (geq && !sup) ? (1ull << j) : 0ull;
        }
        while (mband) {                   // rare: bit-exact reference decision
            int j = __ffsll((long long)mband) - 1;
            mband &= mband - 1;
            float4 b = PB[t * 64 + j];
            float xx1 = fmaxf(r.x, b.x), yy1 = fmaxf(r.y, b.y);
            float xx2 = fminf(r.z, b.z), yy2 = fminf(r.w, b.w);
            float ww = fmaxf(xx2 - xx1, 0.f), hh = fmaxf(yy2 - yy1, 0.f);
            float inter = ww * hh;
            float car = (b.z - b.x) * (b.w - b.y);
            float uni = (ra + car) - inter;
            if ((inter / fmaxf(uni, 1e-9f)) > 0.7f) msup |= (1ull << j);
        }
        while (msup) {                    // scatter to rank positions
            int j = __ffsll((long long)msup) - 1;
            msup &= msup - 1;
            int orank = PR[t * 64 + j];
            int lo = min(myrank, orank), hi = max(myrank, orank);
            atomicOr(&Mimg[(size_t)lo * WPR + (hi >> 6)], 1ull << (hi & 63));
        }
    }
}

// ---------------- K9: greedy NMS (2-bit speculative) + output (fused) -------
// layout: [proposals (8,1000,4) f32][scores (8,1000) f32]
__global__ void __launch_bounds__(256)
k_nmsout(float* __restrict__ out) {
    int img = blockIdx.x;
    __shared__ u64 diag_sh[64];
    __shared__ u64 s_km[63];
    __shared__ int s_kept[POST_NMS];
    __shared__ int s_n;
    __shared__ unsigned sh[256];
    int tid = threadIdx.x;

    if (tid < 32) {                        // warp 0: sequential greedy scan
        int lane = tid;
        const unsigned* vm = g_vmask32 + img * 128;
        u64 r0 = ~((u64)vm[2 * lane] | ((u64)vm[2 * lane + 1] << 32));
        u64 r1 = ~((u64)vm[64 + 2 * lane] | ((u64)vm[65 + 2 * lane] << 32));
        const u64* M = g_mask + (size_t)img * PRE_NMS * WPR;
        u64 nd0 = M[(size_t)(2 * lane) * WPR + 0];
        u64 nd1 = M[(size_t)(2 * lane + 1) * WPR + 0];
        int n = 0;
        for (int ch = 0; ch < 63; ch++) {
            diag_sh[2 * lane] = nd0;
            diag_sh[2 * lane + 1] = nd1;
            __syncwarp();
            if (ch < 62) {
                int base = (ch + 1) * 64;
                int ra2 = base + 2 * lane, rb2 = ra2 + 1;
                nd0 = (ra2 < PRE_NMS) ? M[(size_t)ra2 * WPR + (ch + 1)] : 0ull;
                nd1 = (rb2 < PRE_NMS) ? M[(size_t)rb2 * WPR + (ch + 1)] : 0ull;
            }
            u64 remw = (ch < 32) ? __shfl_sync(0xffffffffu, r0, ch)
                                 : __shfl_sync(0xffffffffu, r1, ch - 32);
            u64 km = 0ull;
#pragma unroll
            for (int b = 0; b < 64; b += 2) {
                u64 d0 = diag_sh[b], d1 = diag_sh[b + 1];
                u64 d01 = d0 | d1;                 // off-chain
                u64 c01 = remw | d1;
                u64 c10 = remw | d0;
                u64 c11 = remw | d01;
                bool k0  = (remw & (1ull << b)) == 0ull;
                bool k1k = (c10  & (1ull << (b + 1))) == 0ull;
                bool k1s = (remw & (1ull << (b + 1))) == 0ull;
                u64 lo  = k0 ? c10 : remw;
                u64 hi2 = k0 ? c11 : c01;
                bool k1 = k0 ? k1k : k1s;
                remw = k1 ? hi2 : lo;
                km |= (k0 ? (1ull << b) : 0ull) | (k1 ? (1ull << (b + 1)) : 0ull);
            }
            // parallel kept-list extraction (rank by popcount)
            {
                bool kb0 = (km >> lane) & 1ull;
                int rk0 = __popcll(km & ((1ull << lane) - 1ull));
                int slot0 = n + rk0;
                if (kb0 && slot0 < POST_NMS) s_kept[slot0] = ch * 64 + lane;
                int l2 = lane + 32;
                bool kb1 = (km >> l2) & 1ull;
                int rk1 = __popcll(km & ((1ull << l2) - 1ull));
                int slot1 = n + rk1;
                if (kb1 && slot1 < POST_NMS) s_kept[slot1] = ch * 64 + l2;
            }
            if (lane == 0) s_km[ch] = km;
            n += __popcll(km);
            if (n >= POST_NMS) break;
            // OR kept rows' full masks into remv, 8-wide batches for MLP
            u64 t = km;
            while (t) {
                int rr[8];
#pragma unroll
                for (int u = 0; u < 8; u++) {
                    if (t) { rr[u] = ch * 64 + (__ffsll((long long)t) - 1); t &= t - 1; }
                    else    rr[u] = -1;
                }
                u64 pa[8], pb[8];
#pragma unroll
                for (int u = 0; u < 8; u++) {
                    if (rr[u] >= 0) {
                        const u64* rp = M + (size_t)rr[u] * WPR;
                        pa[u] = rp[lane];
                        pb[u] = rp[32 + lane];   // word 63 never set -> 0
                    } else { pa[u] = 0ull; pb[u] = 0ull; }
                }
#pragma unroll
                for (int u = 0; u < 8; u++) { r0 |= pa[u]; r1 |= pb[u]; }
            }
            __syncwarp();
        }
        if (lane == 0) s_n = n;
    }
    __syncthreads();

    // ---- output assembly (256 threads) ----
    int n = s_n;
    int lim = n < POST_NMS ? n : POST_NMS;
    for (int s2 = tid; s2 < lim; s2 += 256) {
        int i = s_kept[s2];
        ((float4*)out)[img * POST_NMS + s2] = g_box[img * PRE_NMS + i];
        out[NB * POST_NMS * 4 + img * POST_NMS + s2] = g_prob[img * PRE_NMS + i];
    }
    if (n >= POST_NMS) return;
    // fill with non-kept indices ascending, score = -inf (top_k tie rule)
    unsigned base = 0;
    for (int chunk = 0; chunk < PRE_NMS; chunk += 256) {
        int i = chunk + tid;
        unsigned f = 0u;
        if (i < PRE_NMS) {
            u64 kw = s_km[i >> 6];
            f = ((kw >> (i & 63)) & 1ull) ? 0u : 1u;
        }
        sh[tid] = f;
        __syncthreads();
        for (int off = 1; off < 256; off <<= 1) {
            unsigned vv = (tid >= off) ? sh[tid - off] : 0u;
            __syncthreads();
            sh[tid] += vv;
            __syncthreads();
        }
        unsigned excl = sh[tid] - f;
        int slot = n + (int)(base + excl);
        if (f && slot < POST_NMS) {
            ((float4*)out)[img * POST_NMS + slot] = g_box[img * PRE_NMS + i];
            out[NB * POST_NMS * 4 + img * POST_NMS + slot] =
                __int_as_float(0xff800000);  // -inf
        }
        base += sh[255];
        __syncthreads();
    }
}

// ---------------- host ------------------------------------------------------
extern "C" void kernel_launch(void* const* d_in, const int* in_sizes, int n_in,
                              void* d_out, int out_size) {
    const float* obj     = (const float*)d_in[0];   // (8, 750000)
    const float* deltas  = (const float*)d_in[1];   // (8, 750000, 4)
    const float* anchors = (const float*)d_in[2];   // (750000, 4)
    float* out = (float*)d_out;

    k_zero<<<2048, 512>>>();
    k_hist_c<<<dim3(144, NB), 256>>>(obj);
    k_select_c<<<NB, 32>>>();
    k_hist_f<<<dim3(144, NB), 256>>>(obj);
    k_select_f_compact<<<NB, 256>>>();

    cudaFuncSetAttribute(k_sortdecode, cudaFuncAttributeMaxDynamicSharedMemorySize,
                         CAND_CAP * (int)sizeof(u64));
    k_sortdecode<<<NB, 1024, CAND_CAP * sizeof(u64)>>>(deltas, anchors);

    k_perm<<<NB, 256>>>();
    k_hull<<<NB, 512>>>();
    k_iou_sparse<<<dim3(32, NB), 128>>>();
    k_nmsout<<<NB, 256>>>(out);
}

// round 11
// speedup vs baseline: 1.4218x; 1.3882x over previous
#include <cuda_runtime.h>
#include <cstdint>
#include <cstddef>

#define NB 8
#define NA 750000
#define PRE_NMS 4000
#define POST_NMS 1000
#define MIN_SIZE 0.001f
#define IMG_WF 1000.0f
#define IMG_HF 1000.0f
#define CAND_CAP 8192
#define BC_CAP 24576
#define SBUF 1024
#define WPR 64          /* mask words per row (63 used; word 63 never written -> 0) */
#define BBOX_CLIP 4.135166556742356f   /* log(1000/16) */
#define PEND 24         /* pipelined OR batch width (rows) */
#define C_HI 0.700007f
#define C_LO 0.699993f

typedef unsigned long long u64;

// ---------------- scratch (static device allocations; zero-initialized) ----
__device__ unsigned g_hist_c[NB * 1024];
__device__ unsigned g_hist_f[NB * 1024];
__device__ unsigned g_bucket_c[NB];
__device__ unsigned g_above_c[NB];
__device__ int      g_cand_cnt[NB];
__device__ int      g_bcnt[NB];
__device__ u64      g_cand[NB * CAND_CAP];
__device__ u64      g_bcand[NB * BC_CAP];
__device__ float4   g_box[NB * PRE_NMS];
__device__ float    g_prob[NB * PRE_NMS];
__device__ unsigned g_vmask32[NB * 128];
__device__ u64      g_mask[(size_t)NB * PRE_NMS * WPR];  // 16 MB

// monotone key: larger float -> larger unsigned
__device__ __forceinline__ unsigned fkey(float f) {
    unsigned u = __float_as_uint(f);
    return u ^ ((u & 0x80000000u) ? 0xFFFFFFFFu : 0x80000000u);
}
__device__ __forceinline__ float unkey(unsigned k) {
    return __uint_as_float((k & 0x80000000u) ? (k ^ 0x80000000u) : ~k);
}

// ---------------- K0: zero small scratch ------------------------------------
__global__ void k_zero() {
    int t = blockIdx.x * blockDim.x + threadIdx.x;
    for (int i = t; i < NB * 1024; i += gridDim.x * blockDim.x) {
        g_hist_c[i] = 0u;
        g_hist_f[i] = 0u;
    }
    if (t < NB) { g_cand_cnt[t] = 0; g_bcnt[t] = 0; }
}

// ---------------- K1: coarse 10-bit histogram (float4, 2x unroll) -----------
__global__ void k_hist_c(const float* __restrict__ obj) {
    __shared__ unsigned h[1024];
    for (int t = threadIdx.x; t < 1024; t += blockDim.x) h[t] = 0u;
    __syncthreads();
    int img = blockIdx.y;
    const float4* o = (const float4*)(obj + (size_t)img * NA);
    int stride = gridDim.x * blockDim.x;
    int i = blockIdx.x * blockDim.x + threadIdx.x;
    for (; i + stride < NA / 4; i += 2 * stride) {
        float4 v0 = o[i];
        float4 v1 = o[i + stride];
        atomicAdd(&h[fkey(v0.x) >> 22], 1u);
        atomicAdd(&h[fkey(v0.y) >> 22], 1u);
        atomicAdd(&h[fkey(v0.z) >> 22], 1u);
        atomicAdd(&h[fkey(v0.w) >> 22], 1u);
        atomicAdd(&h[fkey(v1.x) >> 22], 1u);
        atomicAdd(&h[fkey(v1.y) >> 22], 1u);
        atomicAdd(&h[fkey(v1.z) >> 22], 1u);
        atomicAdd(&h[fkey(v1.w) >> 22], 1u);
    }
    if (i < NA / 4) {
        float4 v = o[i];
        atomicAdd(&h[fkey(v.x) >> 22], 1u);
        atomicAdd(&h[fkey(v.y) >> 22], 1u);
        atomicAdd(&h[fkey(v.z) >> 22], 1u);
        atomicAdd(&h[fkey(v.w) >> 22], 1u);
    }
    __syncthreads();
    for (int t = threadIdx.x; t < 1024; t += blockDim.x)
        if (h[t]) atomicAdd(&g_hist_c[img * 1024 + t], h[t]);
}

// ---------------- K2: pick coarse boundary bucket (1 warp/image) ------------
__global__ void k_select_c() {
    int img = blockIdx.x, lane = threadIdx.x;
    const unsigned* H = g_hist_c + img * 1024;
    unsigned part = 0;
    for (int r = lane * 32; r < lane * 32 + 32; r++) part += H[1023 - r];
    unsigned inc = part;
    for (int off = 1; off < 32; off <<= 1) {
        unsigned v = __shfl_up_sync(0xffffffffu, inc, off);
        if (lane >= off) inc += v;
    }
    unsigned needed = (unsigned)PRE_NMS;
    unsigned excl = inc - part;
    if (inc >= needed && excl < needed) {
        unsigned acc = excl;
        for (int r = lane * 32; r < lane * 32 + 32; r++) {
            unsigned hv = H[1023 - r];
            if (acc + hv >= needed) {
                g_bucket_c[img] = (unsigned)(1023 - r);
                g_above_c[img]  = acc;
                break;
            }
            acc += hv;
        }
    }
}

// ---------------- K3: fine histogram + collect (block-staged) ---------------
__global__ void k_hist_f(const float* __restrict__ obj) {
    __shared__ unsigned h[1024];
    __shared__ u64 su[SBUF], sb[SBUF];
    __shared__ int scu, scb, gu, gb;
    for (int t = threadIdx.x; t < 1024; t += blockDim.x) h[t] = 0u;
    if (threadIdx.x == 0) { scu = 0; scb = 0; }
    __syncthreads();
    int img = blockIdx.y;
    unsigned c = g_bucket_c[img];
    const float4* o = (const float4*)(obj + (size_t)img * NA);
    int stride = gridDim.x * blockDim.x;
    for (int i = blockIdx.x * blockDim.x + threadIdx.x; i < NA / 4; i += stride) {
        float4 v = o[i];
        unsigned k0 = fkey(v.x), k1 = fkey(v.y), k2 = fkey(v.z), k3 = fkey(v.w);
        unsigned mx = max(max(k0, k1), max(k2, k3));
        if ((mx >> 22) < c) continue;          // fast path: ~92% of iterations
#pragma unroll
        for (int j = 0; j < 4; j++) {
            unsigned key = (j == 0) ? k0 : (j == 1) ? k1 : (j == 2) ? k2 : k3;
            unsigned cb = key >> 22;
            if (cb < c) continue;
            u64 e = ((u64)key << 32) | (unsigned)(~(unsigned)(4 * i + j));
            if (cb > c) {
                int p = atomicAdd(&scu, 1);
                if (p < SBUF) su[p] = e;
                else {
                    int q = atomicAdd(&g_cand_cnt[img], 1);
                    if (q < CAND_CAP) g_cand[img * CAND_CAP + q] = e;
                }
            } else {
                atomicAdd(&h[(key >> 12) & 1023u], 1u);
                int p = atomicAdd(&scb, 1);
                if (p < SBUF) sb[p] = e;
                else {
                    int q = atomicAdd(&g_bcnt[img], 1);
                    if (q < BC_CAP) g_bcand[img * BC_CAP + q] = e;
                }
            }
        }
    }
    __syncthreads();
    if (threadIdx.x == 0) {
        int a = scu < SBUF ? scu : SBUF;
        gu = atomicAdd(&g_cand_cnt[img], a);
        int b2 = scb < SBUF ? scb : SBUF;
        gb = atomicAdd(&g_bcnt[img], b2);
    }
    __syncthreads();
    int nu = scu < SBUF ? scu : SBUF;
    for (int p = threadIdx.x; p < nu; p += blockDim.x) {
        int q = gu + p;
        if (q < CAND_CAP) g_cand[img * CAND_CAP + q] = su[p];
    }
    int nb = scb < SBUF ? scb : SBUF;
    for (int p = threadIdx.x; p < nb; p += blockDim.x) {
        int q = gb + p;
        if (q < BC_CAP) g_bcand[img * BC_CAP + q] = sb[p];
    }
    for (int t = threadIdx.x; t < 1024; t += blockDim.x)
        if (h[t]) atomicAdd(&g_hist_f[img * 1024 + t], h[t]);
}

// ---------------- K4: fine select + boundary filter (fused) -----------------
__global__ void k_select_f_compact() {
    int img = blockIdx.x;
    int lane = threadIdx.x & 31;
    __shared__ unsigned sT;
    if (threadIdx.x < 32) {               // warp 0: pick fine bucket
        const unsigned* H = g_hist_f + img * 1024;
        unsigned part = 0;
        for (int r = lane * 32; r < lane * 32 + 32; r++) part += H[1023 - r];
        unsigned inc = part;
        for (int off = 1; off < 32; off <<= 1) {
            unsigned v = __shfl_up_sync(0xffffffffu, inc, off);
            if (lane >= off) inc += v;
        }
        unsigned base   = g_above_c[img];
        unsigned needed = (unsigned)PRE_NMS - base;
        unsigned excl = inc - part;
        if (inc >= needed && excl < needed) {
            unsigned acc = excl;
            for (int r = lane * 32; r < lane * 32 + 32; r++) {
                unsigned hv = H[1023 - r];
                if (acc + hv >= needed) {
                    sT = (g_bucket_c[img] << 10) | (unsigned)(1023 - r);
                    break;
                }
                acc += hv;
            }
        }
    }
    __syncthreads();
    unsigned T = sT;
    int cnt = g_bcnt[img]; if (cnt > BC_CAP) cnt = BC_CAP;
    int nIter = (cnt + blockDim.x - 1) / blockDim.x;
    for (int it = 0; it < nIter; it++) {
        int i = it * blockDim.x + threadIdx.x;
        bool take = false;
        u64 e = 0ull;
        if (i < cnt) {
            e = g_bcand[img * BC_CAP + i];
            take = ((unsigned)(e >> 44) >= T);
        }
        unsigned m = __ballot_sync(0xffffffffu, take);
        if (m) {
            int ldr = __ffs(m) - 1;
            int base = 0;
            if (lane == ldr) base = atomicAdd(&g_cand_cnt[img], __popc(m));
            base = __shfl_sync(0xffffffffu, base, ldr);
            if (take) {
                int p = base + __popc(m & ((1u << lane) - 1u));
                if (p < CAND_CAP) g_cand[img * CAND_CAP + p] = e;
            }
        }
    }
}

// ---------------- K5: bitonic sort + decode + clip + sigmoid (fused) --------
__global__ void __launch_bounds__(1024, 1)
k_sortdecode(const float* __restrict__ deltas,
             const float* __restrict__ anchors) {
    extern __shared__ u64 s[];
    int img = blockIdx.x;
    int cnt = g_cand_cnt[img];
    if (cnt > CAND_CAP) cnt = CAND_CAP;
    unsigned S = (cnt <= 4096) ? 4096u : (unsigned)CAND_CAP;
    for (unsigned t = threadIdx.x; t < S; t += blockDim.x)
        s[t] = (t < (unsigned)cnt) ? g_cand[img * CAND_CAP + t] : 0ull;
    __syncthreads();
    for (unsigned k = 2; k <= S; k <<= 1) {
        for (unsigned j = k >> 1; j > 0; j >>= 1) {
            for (unsigned idx = threadIdx.x; idx < S; idx += blockDim.x) {
                unsigned ixj = idx ^ j;
                if (ixj > idx) {
                    u64 a = s[idx], b = s[ixj];
                    bool blk = ((idx & k) == 0u);     // descending overall
                    if (blk ? (a < b) : (a > b)) { s[idx] = b; s[ixj] = a; }
                }
            }
            __syncthreads();
        }
    }
    // decode top-4000 directly from sorted smem
    for (int t = threadIdx.x; t < 4096; t += blockDim.x) {
        bool inr = (t < PRE_NMS);
        u64 key = inr ? s[t] : 0ull;
        int idx = inr ? (int)(~(unsigned)key) : 0;
        float4 a = ((const float4*)anchors)[idx];
        float4 d = ((const float4*)deltas)[(size_t)img * NA + idx];
        float w = a.z - a.x, h = a.w - a.y;
        float cx = a.x + 0.5f * w, cy = a.y + 0.5f * h;
        float dw = fminf(d.z, BBOX_CLIP), dh = fminf(d.w, BBOX_CLIP);
        float pcx = d.x * w + cx, pcy = d.y * h + cy;
        float pw = expf(dw) * w, ph = expf(dh) * h;
        float x1 = pcx - 0.5f * pw, y1 = pcy - 0.5f * ph;
        float x2 = pcx + 0.5f * pw, y2 = pcy + 0.5f * ph;
        x1 = fminf(fmaxf(x1, 0.f), IMG_WF);
        y1 = fminf(fmaxf(y1, 0.f), IMG_HF);
        x2 = fminf(fmaxf(x2, 0.f), IMG_WF);
        y2 = fminf(fmaxf(y2, 0.f), IMG_HF);
        bool validb = false;
        if (inr) {
            g_box[img * PRE_NMS + t] = make_float4(x1, y1, x2, y2);
            validb = ((x2 - x1) >= MIN_SIZE) && ((y2 - y1) >= MIN_SIZE);
            float sc = unkey((unsigned)(key >> 32));
            g_prob[img * PRE_NMS + t] = 1.f / (1.f + expf(-sc));
        }
        unsigned bb = __ballot_sync(0xffffffffu, validb);
        if ((threadIdx.x & 31) == 0 && inr)
            g_vmask32[img * 128 + (t >> 5)] = bb;
    }
}

// ---------------- K6: dense IoU suppression bitmask (shaved loop) -----------
// sup: inter > c*(ra+car-inter)  <=>  (1+c)*inter - c*ra > c*car
__global__ void k_iou() {
    int img = blockIdx.z, rb = blockIdx.y, cb = blockIdx.x;
    if (cb * 64 + 64 <= rb * 128) return;  // entire col-block below diagonal
    __shared__ float4 cbox[64];
    __shared__ float2 csc[64];
    int col0 = cb * 64;
    if (threadIdx.x < 64) {
        int c = col0 + threadIdx.x;
        float4 q = (c < PRE_NMS) ? g_box[img * PRE_NMS + c] : make_float4(0, 0, 0, 0);
        cbox[threadIdx.x] = q;
        float car = (q.z - q.x) * (q.w - q.y);
        csc[threadIdx.x] = make_float2(C_HI * car, C_LO * car);
    }
    __syncthreads();
    int row = rb * 128 + threadIdx.x;
    if (row >= PRE_NMS) return;
    if (col0 + 63 <= row) return;          // this row's word all below/equal diag
    float4 r = g_box[img * PRE_NMS + row];
    float ra = (r.z - r.x) * (r.w - r.y);
    float nra_hi = -C_HI * ra;
    float nra_lo = -C_LO * ra;
    unsigned mlo = 0u, mhi = 0u, blo = 0u, bhi = 0u;
#pragma unroll 16
    for (int j = 0; j < 64; j++) {
        float4 b = cbox[j];
        float2 sc = csc[j];
        float xx1 = fmaxf(r.x, b.x), yy1 = fmaxf(r.y, b.y);
        float xx2 = fminf(r.z, b.z), yy2 = fminf(r.w, b.w);
        float ww = fmaxf(xx2 - xx1, 0.f), hh = fmaxf(yy2 - yy1, 0.f);
        float inter = ww * hh;
        bool sup = __fmaf_rn(1.0f + C_HI, inter, nra_hi) > sc.x;
        bool geq = __fmaf_rn(1.0f + C_LO, inter, nra_lo) >= sc.y;
        unsigned bit = 1u << (j & 31);
        if (j < 32) { mlo |= sup ? bit : 0u; blo |= geq ? bit : 0u; }
        else        { mhi |= sup ? bit : 0u; bhi |= geq ? bit : 0u; }
    }
    u64 msup  = ((u64)mhi << 32) | mlo;
    u64 mband = (((u64)bhi << 32) | blo) & ~msup;
    int rel = row - col0;                  // keep only cols strictly above diag
    if (rel >= 0) {
        u64 hi = (rel >= 63) ? 0ull : (~0ull << (rel + 1));
        msup &= hi;
        mband &= hi;
    }
    while (mband) {                        // rare: bit-exact reference decision
        int j = __ffsll((long long)mband) - 1;
        mband &= mband - 1;
        float4 b = cbox[j];
        float carj = (b.z - b.x) * (b.w - b.y);
        float xx1 = fmaxf(r.x, b.x), yy1 = fmaxf(r.y, b.y);
        float xx2 = fminf(r.z, b.z), yy2 = fminf(r.w, b.w);
        float ww = fmaxf(xx2 - xx1, 0.f), hh = fmaxf(yy2 - yy1, 0.f);
        float inter = ww * hh;
        float uni = (ra + carj) - inter;
        if ((inter / fmaxf(uni, 1e-9f)) > 0.7f) msup |= (1ull << j);
    }
    g_mask[((size_t)img * PRE_NMS + row) * WPR + cb] = msup;
}

// ---------------- K7: greedy NMS (pipelined OR) + output (fused) ------------
// OR-loads for chunk ch's kept rows are ISSUED at end of iteration ch and
// CONSUMED at the start of iteration ch+1 (before the remw shfl), hiding the
// L2 latency behind extraction/prefetch. Resolve of ch+1 needs exactly the
// contributions of keeps <= ch, which consumption provides.
// layout: [proposals (8,1000,4) f32][scores (8,1000) f32]
__global__ void __launch_bounds__(256)
k_nmsout(float* __restrict__ out) {
    int img = blockIdx.x;
    __shared__ u64 diag_sh[64];
    __shared__ u64 s_km[63];
    __shared__ int s_kept[POST_NMS];
    __shared__ int s_n;
    __shared__ unsigned sh[256];
    int tid = threadIdx.x;

    if (tid < 32) {                        // warp 0: sequential greedy scan
        int lane = tid;
        const unsigned* vm = g_vmask32 + img * 128;
        u64 r0 = ~((u64)vm[2 * lane] | ((u64)vm[2 * lane + 1] << 32));
        u64 r1 = ~((u64)vm[64 + 2 * lane] | ((u64)vm[65 + 2 * lane] << 32));
        const u64* M = g_mask + (size_t)img * PRE_NMS * WPR;
        u64 nd0 = M[(size_t)(2 * lane) * WPR + 0];
        u64 nd1 = M[(size_t)(2 * lane + 1) * WPR + 0];
        u64 pa[PEND], pb[PEND];            // pending OR loads (prev chunk keeps)
#pragma unroll
        for (int u = 0; u < PEND; u++) { pa[u] = 0ull; pb[u] = 0ull; }
        int n = 0;
        for (int ch = 0; ch < 63; ch++) {
            diag_sh[2 * lane] = nd0;
            diag_sh[2 * lane + 1] = nd1;
            __syncwarp();
            if (ch < 62) {                 // prefetch next chunk's diag
                int base = (ch + 1) * 64;
                int ra2 = base + 2 * lane, rb2 = ra2 + 1;
                nd0 = (ra2 < PRE_NMS) ? M[(size_t)ra2 * WPR + (ch + 1)] : 0ull;
                nd1 = (rb2 < PRE_NMS) ? M[(size_t)rb2 * WPR + (ch + 1)] : 0ull;
            }
            // consume pending OR loads from chunk ch-1's keeps
#pragma unroll
            for (int u = 0; u < PEND; u++) { r0 |= pa[u]; r1 |= pb[u]; }
            u64 remw = (ch < 32) ? __shfl_sync(0xffffffffu, r0, ch)
                                 : __shfl_sync(0xffffffffu, r1, ch - 32);
            u64 km = 0ull;
#pragma unroll
            for (int b = 0; b < 64; b += 2) {
                u64 d0 = diag_sh[b], d1 = diag_sh[b + 1];
                u64 d01 = d0 | d1;                 // off-chain
                u64 c01 = remw | d1;
                u64 c10 = remw | d0;
                u64 c11 = remw | d01;
                bool k0  = (remw & (1ull << b)) == 0ull;
                bool k1k = (c10  & (1ull << (b + 1))) == 0ull;
                bool k1s = (remw & (1ull << (b + 1))) == 0ull;
                u64 lo  = k0 ? c10 : remw;
                u64 hi2 = k0 ? c11 : c01;
                bool k1 = k0 ? k1k : k1s;
                remw = k1 ? hi2 : lo;
                km |= (k0 ? (1ull << b) : 0ull) | (k1 ? (1ull << (b + 1)) : 0ull);
            }
            // parallel kept-list extraction (rank by popcount)
            {
                bool kb0 = (km >> lane) & 1ull;
                int rk0 = __popcll(km & ((1ull << lane) - 1ull));
                int slot0 = n + rk0;
                if (kb0 && slot0 < POST_NMS) s_kept[slot0] = ch * 64 + lane;
                int l2 = lane + 32;
                bool kb1 = (km >> l2) & 1ull;
                int rk1 = __popcll(km & ((1ull << l2) - 1ull));
                int slot1 = n + rk1;
                if (kb1 && slot1 < POST_NMS) s_kept[slot1] = ch * 64 + l2;
            }
            if (lane == 0) s_km[ch] = km;
            n += __popcll(km);
            if (n >= POST_NMS) break;
            // issue OR loads for this chunk's keeps (consumed next iteration)
            u64 t = km;
#pragma unroll
            for (int u = 0; u < PEND; u++) {
                int rr = -1;
                if (t) { rr = ch * 64 + (__ffsll((long long)t) - 1); t &= t - 1; }
                if (rr >= 0) {
                    const u64* rp = M + (size_t)rr * WPR;
                    pa[u] = rp[lane];
                    pb[u] = rp[32 + lane];   // word 63 never written -> 0
                } else { pa[u] = 0ull; pb[u] = 0ull; }
            }
            // overflow (>PEND keeps in one chunk): consume immediately
            while (t) {
                int rr8[8];
#pragma unroll
                for (int u = 0; u < 8; u++) {
                    if (t) { rr8[u] = ch * 64 + (__ffsll((long long)t) - 1); t &= t - 1; }
                    else    rr8[u] = -1;
                }
                u64 qa[8], qb[8];
#pragma unroll
                for (int u = 0; u < 8; u++) {
                    if (rr8[u] >= 0) {
                        const u64* rp = M + (size_t)rr8[u] * WPR;
                        qa[u] = rp[lane];
                        qb[u] = rp[32 + lane];
                    } else { qa[u] = 0ull; qb[u] = 0ull; }
                }
#pragma unroll
                for (int u = 0; u < 8; u++) { r0 |= qa[u]; r1 |= qb[u]; }
            }
            __syncwarp();
        }
        if (lane == 0) s_n = n;
    }
    __syncthreads();

    // ---- output assembly (256 threads) ----
    int n = s_n;
    int lim = n < POST_NMS ? n : POST_NMS;
    for (int s2 = tid; s2 < lim; s2 += 256) {
        int i = s_kept[s2];
        ((float4*)out)[img * POST_NMS + s2] = g_box[img * PRE_NMS + i];
        out[NB * POST_NMS * 4 + img * POST_NMS + s2] = g_prob[img * PRE_NMS + i];
    }
    if (n >= POST_NMS) return;
    // fill with non-kept indices ascending, score = -inf (top_k tie rule)
    unsigned base = 0;
    for (int chunk = 0; chunk < PRE_NMS; chunk += 256) {
        int i = chunk + tid;
        unsigned f = 0u;
        if (i < PRE_NMS) {
            u64 kw = s_km[i >> 6];
            f = ((kw >> (i & 63)) & 1ull) ? 0u : 1u;
        }
        sh[tid] = f;
        __syncthreads();
        for (int off = 1; off < 256; off <<= 1) {
            unsigned vv = (tid >= off) ? sh[tid - off] : 0u;
            __syncthreads();
            sh[tid] += vv;
            __syncthreads();
        }
        unsigned excl = sh[tid] - f;
        int slot = n + (int)(base + excl);
        if (f && slot < POST_NMS) {
            ((float4*)out)[img * POST_NMS + slot] = g_box[img * PRE_NMS + i];
            out[NB * POST_NMS * 4 + img * POST_NMS + slot] =
                __int_as_float(0xff800000);  // -inf
        }
        base += sh[255];
        __syncthreads();
    }
}

// ---------------- host ------------------------------------------------------
extern "C" void kernel_launch(void* const* d_in, const int* in_sizes, int n_in,
                              void* d_out, int out_size) {
    const float* obj     = (const float*)d_in[0];   // (8, 750000)
    const float* deltas  = (const float*)d_in[1];   // (8, 750000, 4)
    const float* anchors = (const float*)d_in[2];   // (750000, 4)
    float* out = (float*)d_out;

    k_zero<<<8, 1024>>>();
    k_hist_c<<<dim3(144, NB), 256>>>(obj);
    k_select_c<<<NB, 32>>>();
    k_hist_f<<<dim3(144, NB), 256>>>(obj);
    k_select_f_compact<<<NB, 256>>>();

    cudaFuncSetAttribute(k_sortdecode, cudaFuncAttributeMaxDynamicSharedMemorySize,
                         CAND_CAP * (int)sizeof(u64));
    k_sortdecode<<<NB, 1024, CAND_CAP * sizeof(u64)>>>(deltas, anchors);

    k_iou<<<dim3(63, 32, NB), 128>>>();
    k_nmsout<<<NB, 256>>>(out);
}

// round 12
// speedup vs baseline: 1.5721x; 1.1057x over previous
#include <cuda_runtime.h>
#include <cstdint>
#include <cstddef>

#define NB 8
#define NA 750000
#define PRE_NMS 4000
#define POST_NMS 1000
#define MIN_SIZE 0.001f
#define IMG_WF 1000.0f
#define IMG_HF 1000.0f
#define CAND_CAP 8192
#define STG_CAP 32768   /* staged candidates (key >= T_STAGE) per image */
#define BC2_CAP 24576   /* fallback boundary-bucket buffer */
#define SBUF 1024
#define WPR 64          /* mask words per row (63 used; word 63 never written -> 0) */
#define BBOX_CLIP 4.135166556742356f   /* log(1000/16) */
#define PEND 24         /* pipelined OR batch width (rows) */
#define C_HI 0.700007f
#define C_LO 0.699993f
#define T_STAGE 0xC0000000u   /* fkey(2.0f): static staging threshold */

typedef unsigned long long u64;

// ---------------- scratch (static device allocations; zero-initialized) ----
__device__ unsigned g_hist_c[NB * 1024];
__device__ unsigned g_hist_f[NB * 1024];   // fallback only
__device__ unsigned g_bucket_c[NB];
__device__ unsigned g_above_c[NB];
__device__ int      g_fbflag[NB];
__device__ int      g_cand_cnt[NB];
__device__ int      g_scnt[NB];            // staged count
__device__ int      g_bcnt2[NB];           // fallback boundary count
__device__ u64      g_cand[NB * CAND_CAP];
__device__ u64      g_stg[NB * STG_CAP];
__device__ u64      g_bcand2[NB * BC2_CAP];
__device__ float4   g_box[NB * PRE_NMS];
__device__ float    g_prob[NB * PRE_NMS];
__device__ unsigned g_vmask32[NB * 128];
__device__ u64      g_mask[(size_t)NB * PRE_NMS * WPR];  // 16 MB

// monotone key: larger float -> larger unsigned
__device__ __forceinline__ unsigned fkey(float f) {
    unsigned u = __float_as_uint(f);
    return u ^ ((u & 0x80000000u) ? 0xFFFFFFFFu : 0x80000000u);
}
__device__ __forceinline__ float unkey(unsigned k) {
    return __uint_as_float((k & 0x80000000u) ? (k ^ 0x80000000u) : ~k);
}

// ---------------- K0: zero small scratch ------------------------------------
__global__ void k_zero() {
    int t = blockIdx.x * blockDim.x + threadIdx.x;
    for (int i = t; i < NB * 1024; i += gridDim.x * blockDim.x) {
        g_hist_c[i] = 0u;
        g_hist_f[i] = 0u;
    }
    if (t < NB) { g_cand_cnt[t] = 0; g_scnt[t] = 0; g_bcnt2[t] = 0; g_fbflag[t] = 0; }
}

// ---------------- K1: coarse histogram + static-threshold staging -----------
__global__ void k_hist_c_stage(const float* __restrict__ obj) {
    __shared__ unsigned h[1024];
    __shared__ u64 su[SBUF];
    __shared__ int sc, gbase;
    for (int t = threadIdx.x; t < 1024; t += blockDim.x) h[t] = 0u;
    if (threadIdx.x == 0) sc = 0;
    __syncthreads();
    int img = blockIdx.y;
    const float4* o = (const float4*)(obj + (size_t)img * NA);
    int stride = gridDim.x * blockDim.x;
    for (int i = blockIdx.x * blockDim.x + threadIdx.x; i < NA / 4; i += stride) {
        float4 v = o[i];
        unsigned k0 = fkey(v.x), k1 = fkey(v.y), k2 = fkey(v.z), k3 = fkey(v.w);
        atomicAdd(&h[k0 >> 22], 1u);
        atomicAdd(&h[k1 >> 22], 1u);
        atomicAdd(&h[k2 >> 22], 1u);
        atomicAdd(&h[k3 >> 22], 1u);
        unsigned mx = max(max(k0, k1), max(k2, k3));
        if (mx >= T_STAGE) {               // rare (~2.3%): stage
#pragma unroll
            for (int j = 0; j < 4; j++) {
                unsigned key = (j == 0) ? k0 : (j == 1) ? k1 : (j == 2) ? k2 : k3;
                if (key < T_STAGE) continue;
                u64 e = ((u64)key << 32) | (unsigned)(~(unsigned)(4 * i + j));
                int p = atomicAdd(&sc, 1);
                if (p < SBUF) su[p] = e;
                else {
                    int q = atomicAdd(&g_scnt[img], 1);
                    if (q < STG_CAP) g_stg[img * STG_CAP + q] = e;
                }
            }
        }
    }
    __syncthreads();
    if (threadIdx.x == 0) {
        int a = sc < SBUF ? sc : SBUF;
        gbase = atomicAdd(&g_scnt[img], a);
    }
    __syncthreads();
    int ns = sc < SBUF ? sc : SBUF;
    for (int p = threadIdx.x; p < ns; p += blockDim.x) {
        int q = gbase + p;
        if (q < STG_CAP) g_stg[img * STG_CAP + q] = su[p];
    }
    for (int t = threadIdx.x; t < 1024; t += blockDim.x)
        if (h[t]) atomicAdd(&g_hist_c[img * 1024 + t], h[t]);
}

// ---------------- K2: fused selects (coarse + fine-from-staged + compact) ---
__global__ void __launch_bounds__(1024) k_selects() {
    int img = blockIdx.x, tid = threadIdx.x, lane = tid & 31;
    __shared__ unsigned h[1024];
    __shared__ unsigned sh_bucket, sh_above, sh_T;
    __shared__ int sh_flag;
    h[tid] = 0u;
    if (tid == 0) sh_flag = 0;
    __syncthreads();
    if (tid < 32) {                        // warp 0: coarse select
        const unsigned* H = g_hist_c + img * 1024;
        unsigned part = 0;
        for (int r = lane * 32; r < lane * 32 + 32; r++) part += H[1023 - r];
        unsigned inc = part;
        for (int off = 1; off < 32; off <<= 1) {
            unsigned v = __shfl_up_sync(0xffffffffu, inc, off);
            if (lane >= off) inc += v;
        }
        unsigned needed = (unsigned)PRE_NMS;
        unsigned excl = inc - part;
        if (inc >= needed && excl < needed) {
            unsigned acc = excl;
            for (int r = lane * 32; r < lane * 32 + 32; r++) {
                unsigned hv = H[1023 - r];
                if (acc + hv >= needed) {
                    sh_bucket = (unsigned)(1023 - r);
                    sh_above  = acc;
                    break;
                }
                acc += hv;
            }
        }
    }
    __syncthreads();
    unsigned bc = sh_bucket;
    int scnt = g_scnt[img];
    if (tid == 0) {
        g_bucket_c[img] = bc;
        g_above_c[img]  = sh_above;
        // fallback iff staged set might not cover the boundary bucket
        if ((bc << 22) < T_STAGE || scnt > STG_CAP) {
            sh_flag = 1;
            g_fbflag[img] = 1;
        }
    }
    __syncthreads();
    if (sh_flag) return;                   // fallback kernels take over
    if (scnt > STG_CAP) scnt = STG_CAP;
    const u64* S = g_stg + img * STG_CAP;
    // fine histogram over staged boundary-bucket entries
    for (int i = tid; i < scnt; i += 1024) {
        unsigned key = (unsigned)(S[i] >> 32);
        if ((key >> 22) == bc) atomicAdd(&h[(key >> 12) & 1023u], 1u);
    }
    __syncthreads();
    if (tid < 32) {                        // warp 0: fine select
        unsigned part = 0;
        for (int r = lane * 32; r < lane * 32 + 32; r++) part += h[1023 - r];
        unsigned inc = part;
        for (int off = 1; off < 32; off <<= 1) {
            unsigned v = __shfl_up_sync(0xffffffffu, inc, off);
            if (lane >= off) inc += v;
        }
        unsigned needed = (unsigned)PRE_NMS - sh_above;
        unsigned excl = inc - part;
        if (inc >= needed && excl < needed) {
            unsigned acc = excl;
            for (int r = lane * 32; r < lane * 32 + 32; r++) {
                unsigned hv = h[1023 - r];
                if (acc + hv >= needed) {
                    sh_T = (bc << 10) | (unsigned)(1023 - r);
                    break;
                }
                acc += hv;
            }
        }
    }
    __syncthreads();
    unsigned T = sh_T;
    // compact staged entries above threshold into g_cand (warp-aggregated)
    int nIter = (scnt + 1023) / 1024;
    for (int it = 0; it < nIter; it++) {
        int i = it * 1024 + tid;
        bool take = false;
        u64 e = 0ull;
        if (i < scnt) {
            e = S[i];
            take = ((unsigned)(e >> 44) >= T);
        }
        unsigned m = __ballot_sync(0xffffffffu, take);
        if (m) {
            int ldr = __ffs(m) - 1;
            int base = 0;
            if (lane == ldr) base = atomicAdd(&g_cand_cnt[img], __popc(m));
            base = __shfl_sync(0xffffffffu, base, ldr);
            if (take) {
                int p = base + __popc(m & ((1u << lane) - 1u));
                if (p < CAND_CAP) g_cand[img * CAND_CAP + p] = e;
            }
        }
    }
}

// ---------------- K3: FALLBACK full fine-hist pass (early-exit normally) ----
__global__ void k_fb_hist(const float* __restrict__ obj) {
    int img = blockIdx.y;
    if (!g_fbflag[img]) return;
    __shared__ unsigned h[1024];
    __shared__ u64 su[SBUF], sb[SBUF];
    __shared__ int scu, scb, gu, gb;
    for (int t = threadIdx.x; t < 1024; t += blockDim.x) h[t] = 0u;
    if (threadIdx.x == 0) { scu = 0; scb = 0; }
    __syncthreads();
    unsigned c = g_bucket_c[img];
    const float4* o = (const float4*)(obj + (size_t)img * NA);
    int stride = gridDim.x * blockDim.x;
    for (int i = blockIdx.x * blockDim.x + threadIdx.x; i < NA / 4; i += stride) {
        float4 v = o[i];
        unsigned k0 = fkey(v.x), k1 = fkey(v.y), k2 = fkey(v.z), k3 = fkey(v.w);
        unsigned mx = max(max(k0, k1), max(k2, k3));
        if ((mx >> 22) < c) continue;
#pragma unroll
        for (int j = 0; j < 4; j++) {
            unsigned key = (j == 0) ? k0 : (j == 1) ? k1 : (j == 2) ? k2 : k3;
            unsigned cb = key >> 22;
            if (cb < c) continue;
            u64 e = ((u64)key << 32) | (unsigned)(~(unsigned)(4 * i + j));
            if (cb > c) {
                int p = atomicAdd(&scu, 1);
                if (p < SBUF) su[p] = e;
                else {
                    int q = atomicAdd(&g_cand_cnt[img], 1);
                    if (q < CAND_CAP) g_cand[img * CAND_CAP + q] = e;
                }
            } else {
                atomicAdd(&h[(key >> 12) & 1023u], 1u);
                int p = atomicAdd(&scb, 1);
                if (p < SBUF) sb[p] = e;
                else {
                    int q = atomicAdd(&g_bcnt2[img], 1);
                    if (q < BC2_CAP) g_bcand2[img * BC2_CAP + q] = e;
                }
            }
        }
    }
    __syncthreads();
    if (threadIdx.x == 0) {
        int a = scu < SBUF ? scu : SBUF;
        gu = atomicAdd(&g_cand_cnt[img], a);
        int b2 = scb < SBUF ? scb : SBUF;
        gb = atomicAdd(&g_bcnt2[img], b2);
    }
    __syncthreads();
    int nu = scu < SBUF ? scu : SBUF;
    for (int p = threadIdx.x; p < nu; p += blockDim.x) {
        int q = gu + p;
        if (q < CAND_CAP) g_cand[img * CAND_CAP + q] = su[p];
    }
    int nb = scb < SBUF ? scb : SBUF;
    for (int p = threadIdx.x; p < nb; p += blockDim.x) {
        int q = gb + p;
        if (q < BC2_CAP) g_bcand2[img * BC2_CAP + q] = sb[p];
    }
    for (int t = threadIdx.x; t < 1024; t += blockDim.x)
        if (h[t]) atomicAdd(&g_hist_f[img * 1024 + t], h[t]);
}

// ---------------- K4: FALLBACK fine select + compact (early-exit normally) --
__global__ void k_fb_select() {
    int img = blockIdx.x;
    if (!g_fbflag[img]) return;
    int lane = threadIdx.x & 31;
    __shared__ unsigned sT;
    if (threadIdx.x < 32) {
        const unsigned* H = g_hist_f + img * 1024;
        unsigned part = 0;
        for (int r = lane * 32; r < lane * 32 + 32; r++) part += H[1023 - r];
        unsigned inc = part;
        for (int off = 1; off < 32; off <<= 1) {
            unsigned v = __shfl_up_sync(0xffffffffu, inc, off);
            if (lane >= off) inc += v;
        }
        unsigned base   = g_above_c[img];
        unsigned needed = (unsigned)PRE_NMS - base;
        unsigned excl = inc - part;
        if (inc >= needed && excl < needed) {
            unsigned acc = excl;
            for (int r = lane * 32; r < lane * 32 + 32; r++) {
                unsigned hv = H[1023 - r];
                if (acc + hv >= needed) {
                    sT = (g_bucket_c[img] << 10) | (unsigned)(1023 - r);
                    break;
                }
                acc += hv;
            }
        }
    }
    __syncthreads();
    unsigned T = sT;
    int cnt = g_bcnt2[img]; if (cnt > BC2_CAP) cnt = BC2_CAP;
    int nIter = (cnt + blockDim.x - 1) / blockDim.x;
    for (int it = 0; it < nIter; it++) {
        int i = it * blockDim.x + threadIdx.x;
        bool take = false;
        u64 e = 0ull;
        if (i < cnt) {
            e = g_bcand2[img * BC2_CAP + i];
            take = ((unsigned)(e >> 44) >= T);
        }
        unsigned m = __ballot_sync(0xffffffffu, take);
        if (m) {
            int ldr = __ffs(m) - 1;
            int base = 0;
            if (lane == ldr) base = atomicAdd(&g_cand_cnt[img], __popc(m));
            base = __shfl_sync(0xffffffffu, base, ldr);
            if (take) {
                int p = base + __popc(m & ((1u << lane) - 1u));
                if (p < CAND_CAP) g_cand[img * CAND_CAP + p] = e;
            }
        }
    }
}

// ---------------- K5: bitonic sort + decode + clip + sigmoid (fused) --------
__global__ void __launch_bounds__(1024, 1)
k_sortdecode(const float* __restrict__ deltas,
             const float* __restrict__ anchors) {
    extern __shared__ u64 s[];
    int img = blockIdx.x;
    int cnt = g_cand_cnt[img];
    if (cnt > CAND_CAP) cnt = CAND_CAP;
    unsigned S = (cnt <= 4096) ? 4096u : (unsigned)CAND_CAP;
    for (unsigned t = threadIdx.x; t < S; t += blockDim.x)
        s[t] = (t < (unsigned)cnt) ? g_cand[img * CAND_CAP + t] : 0ull;
    __syncthreads();
    for (unsigned k = 2; k <= S; k <<= 1) {
        for (unsigned j = k >> 1; j > 0; j >>= 1) {
            for (unsigned idx = threadIdx.x; idx < S; idx += blockDim.x) {
                unsigned ixj = idx ^ j;
                if (ixj > idx) {
                    u64 a = s[idx], b = s[ixj];
                    bool blk = ((idx & k) == 0u);     // descending overall
                    if (blk ? (a < b) : (a > b)) { s[idx] = b; s[ixj] = a; }
                }
            }
            __syncthreads();
        }
    }
    // decode top-4000 directly from sorted smem
    for (int t = threadIdx.x; t < 4096; t += blockDim.x) {
        bool inr = (t < PRE_NMS);
        u64 key = inr ? s[t] : 0ull;
        int idx = inr ? (int)(~(unsigned)key) : 0;
        float4 a = ((const float4*)anchors)[idx];
        float4 d = ((const float4*)deltas)[(size_t)img * NA + idx];
        float w = a.z - a.x, h = a.w - a.y;
        float cx = a.x + 0.5f * w, cy = a.y + 0.5f * h;
        float dw = fminf(d.z, BBOX_CLIP), dh = fminf(d.w, BBOX_CLIP);
        float pcx = d.x * w + cx, pcy = d.y * h + cy;
        float pw = expf(dw) * w, ph = expf(dh) * h;
        float x1 = pcx - 0.5f * pw, y1 = pcy - 0.5f * ph;
        float x2 = pcx + 0.5f * pw, y2 = pcy + 0.5f * ph;
        x1 = fminf(fmaxf(x1, 0.f), IMG_WF);
        y1 = fminf(fmaxf(y1, 0.f), IMG_HF);
        x2 = fminf(fmaxf(x2, 0.f), IMG_WF);
        y2 = fminf(fmaxf(y2, 0.f), IMG_HF);
        bool validb = false;
        if (inr) {
            g_box[img * PRE_NMS + t] = make_float4(x1, y1, x2, y2);
            validb = ((x2 - x1) >= MIN_SIZE) && ((y2 - y1) >= MIN_SIZE);
            float sc = unkey((unsigned)(key >> 32));
            g_prob[img * PRE_NMS + t] = 1.f / (1.f + expf(-sc));
        }
        unsigned bb = __ballot_sync(0xffffffffu, validb);
        if ((threadIdx.x & 31) == 0 && inr)
            g_vmask32[img * 128 + (t >> 5)] = bb;
    }
}

// ---------------- K6: dense IoU bitmask (256 rows/block, shaved loop) -------
// sup: inter > c*(ra+car-inter)  <=>  (1+c)*inter - c*ra > c*car
__global__ void __launch_bounds__(256) k_iou() {
    int img = blockIdx.z, rb = blockIdx.y, cb = blockIdx.x;
    if (cb * 64 + 64 <= rb * 256) return;  // entire col-block below diagonal
    __shared__ float4 cbox[64];
    __shared__ float2 csc[64];
    int col0 = cb * 64;
    if (threadIdx.x < 64) {
        int c = col0 + threadIdx.x;
        float4 q = (c < PRE_NMS) ? g_box[img * PRE_NMS + c] : make_float4(0, 0, 0, 0);
        cbox[threadIdx.x] = q;
        float car = (q.z - q.x) * (q.w - q.y);
        csc[threadIdx.x] = make_float2(C_HI * car, C_LO * car);
    }
    __syncthreads();
    int row = rb * 256 + threadIdx.x;
    if (row >= PRE_NMS) return;
    if (col0 + 63 <= row) return;          // this row's word all below/equal diag
    float4 r = g_box[img * PRE_NMS + row];
    float ra = (r.z - r.x) * (r.w - r.y);
    float nra_hi = -C_HI * ra;
    float nra_lo = -C_LO * ra;
    unsigned mlo = 0u, mhi = 0u, blo = 0u, bhi = 0u;
#pragma unroll 16
    for (int j = 0; j < 64; j++) {
        float4 b = cbox[j];
        float2 sc = csc[j];
        float xx1 = fmaxf(r.x, b.x), yy1 = fmaxf(r.y, b.y);
        float xx2 = fminf(r.z, b.z), yy2 = fminf(r.w, b.w);
        float ww = fmaxf(xx2 - xx1, 0.f), hh = fmaxf(yy2 - yy1, 0.f);
        float inter = ww * hh;
        bool sup = __fmaf_rn(1.0f + C_HI, inter, nra_hi) > sc.x;
        bool geq = __fmaf_rn(1.0f + C_LO, inter, nra_lo) >= sc.y;
        unsigned bit = 1u << (j & 31);
        if (j < 32) { mlo |= sup ? bit : 0u; blo |= geq ? bit : 0u; }
        else        { mhi |= sup ? bit : 0u; bhi |= geq ? bit : 0u; }
    }
    u64 msup  = ((u64)mhi << 32) | mlo;
    u64 mband = (((u64)bhi << 32) | blo) & ~msup;
    int rel = row - col0;                  // keep only cols strictly above diag
    if (rel >= 0) {
        u64 hi = (rel >= 63) ? 0ull : (~0ull << (rel + 1));
        msup &= hi;
        mband &= hi;
    }
    while (mband) {                        // rare: bit-exact reference decision
        int j = __ffsll((long long)mband) - 1;
        mband &= mband - 1;
        float4 b = cbox[j];
        float carj = (b.z - b.x) * (b.w - b.y);
        float xx1 = fmaxf(r.x, b.x), yy1 = fmaxf(r.y, b.y);
        float xx2 = fminf(r.z, b.z), yy2 = fminf(r.w, b.w);
        float ww = fmaxf(xx2 - xx1, 0.f), hh = fmaxf(yy2 - yy1, 0.f);
        float inter = ww * hh;
        float uni = (ra + carj) - inter;
        if ((inter / fmaxf(uni, 1e-9f)) > 0.7f) msup |= (1ull << j);
    }
    g_mask[((size_t)img * PRE_NMS + row) * WPR + cb] = msup;
}

// ---------------- K7: greedy NMS (pipelined OR) + output (fused) ------------
// layout: [proposals (8,1000,4) f32][scores (8,1000) f32]
__global__ void __launch_bounds__(256)
k_nmsout(float* __restrict__ out) {
    int img = blockIdx.x;
    __shared__ u64 diag_sh[64];
    __shared__ u64 s_km[63];
    __shared__ int s_kept[POST_NMS];
    __shared__ int s_n;
    __shared__ unsigned sh[256];
    int tid = threadIdx.x;

    if (tid < 32) {                        // warp 0: sequential greedy scan
        int lane = tid;
        const unsigned* vm = g_vmask32 + img * 128;
        u64 r0 = ~((u64)vm[2 * lane] | ((u64)vm[2 * lane + 1] << 32));
        u64 r1 = ~((u64)vm[64 + 2 * lane] | ((u64)vm[65 + 2 * lane] << 32));
        const u64* M = g_mask + (size_t)img * PRE_NMS * WPR;
        u64 nd0 = M[(size_t)(2 * lane) * WPR + 0];
        u64 nd1 = M[(size_t)(2 * lane + 1) * WPR + 0];
        u64 pa[PEND], pb[PEND];            // pending OR loads (prev chunk keeps)
#pragma unroll
        for (int u = 0; u < PEND; u++) { pa[u] = 0ull; pb[u] = 0ull; }
        int n = 0;
        for (int ch = 0; ch < 63; ch++) {
            diag_sh[2 * lane] = nd0;
            diag_sh[2 * lane + 1] = nd1;
            __syncwarp();
            if (ch < 62) {                 // prefetch next chunk's diag
                int base = (ch + 1) * 64;
                int ra2 = base + 2 * lane, rb2 = ra2 + 1;
                nd0 = (ra2 < PRE_NMS) ? M[(size_t)ra2 * WPR + (ch + 1)] : 0ull;
                nd1 = (rb2 < PRE_NMS) ? M[(size_t)rb2 * WPR + (ch + 1)] : 0ull;
            }
            // consume pending OR loads from chunk ch-1's keeps
#pragma unroll
            for (int u = 0; u < PEND; u++) { r0 |= pa[u]; r1 |= pb[u]; }
            u64 remw = (ch < 32) ? __shfl_sync(0xffffffffu, r0, ch)
                                 : __shfl_sync(0xffffffffu, r1, ch - 32);
            u64 km = 0ull;
#pragma unroll
            for (int b = 0; b < 64; b += 2) {
                u64 d0 = diag_sh[b], d1 = diag_sh[b + 1];
                u64 d01 = d0 | d1;                 // off-chain
                u64 c01 = remw | d1;
                u64 c10 = remw | d0;
                u64 c11 = remw | d01;
                bool k0  = (remw & (1ull << b)) == 0ull;
                bool k1k = (c10  & (1ull << (b + 1))) == 0ull;
                bool k1s = (remw & (1ull << (b + 1))) == 0ull;
                u64 lo  = k0 ? c10 : remw;
                u64 hi2 = k0 ? c11 : c01;
                bool k1 = k0 ? k1k : k1s;
                remw = k1 ? hi2 : lo;
                km |= (k0 ? (1ull << b) : 0ull) | (k1 ? (1ull << (b + 1)) : 0ull);
            }
            // parallel kept-list extraction (rank by popcount)
            {
                bool kb0 = (km >> lane) & 1ull;
                int rk0 = __popcll(km & ((1ull << lane) - 1ull));
                int slot0 = n + rk0;
                if (kb0 && slot0 < POST_NMS) s_kept[slot0] = ch * 64 + lane;
                int l2 = lane + 32;
                bool kb1 = (km >> l2) & 1ull;
                int rk1 = __popcll(km & ((1ull << l2) - 1ull));
                int slot1 = n + rk1;
                if (kb1 && slot1 < POST_NMS) s_kept[slot1] = ch * 64 + l2;
            }
            if (lane == 0) s_km[ch] = km;
            n += __popcll(km);
            if (n >= POST_NMS) break;
            // issue OR loads for this chunk's keeps (consumed next iteration)
            u64 t = km;
#pragma unroll
            for (int u = 0; u < PEND; u++) {
                int rr = -1;
                if (t) { rr = ch * 64 + (__ffsll((long long)t) - 1); t &= t - 1; }
                if (rr >= 0) {
                    const u64* rp = M + (size_t)rr * WPR;
                    pa[u] = rp[lane];
                    pb[u] = rp[32 + lane];   // word 63 never written -> 0
                } else { pa[u] = 0ull; pb[u] = 0ull; }
            }
            // overflow (>PEND keeps in one chunk): consume immediately
            while (t) {
                int rr8[8];
#pragma unroll
                for (int u = 0; u < 8; u++) {
                    if (t) { rr8[u] = ch * 64 + (__ffsll((long long)t) - 1); t &= t - 1; }
                    else    rr8[u] = -1;
                }
                u64 qa[8], qb[8];
#pragma unroll
                for (int u = 0; u < 8; u++) {
                    if (rr8[u] >= 0) {
                        const u64* rp = M + (size_t)rr8[u] * WPR;
                        qa[u] = rp[lane];
                        qb[u] = rp[32 + lane];
                    } else { qa[u] = 0ull; qb[u] = 0ull; }
                }
#pragma unroll
                for (int u = 0; u < 8; u++) { r0 |= qa[u]; r1 |= qb[u]; }
            }
            __syncwarp();
        }
        if (lane == 0) s_n = n;
    }
    __syncthreads();

    // ---- output assembly (256 threads) ----
    int n = s_n;
    int lim = n < POST_NMS ? n : POST_NMS;
    for (int s2 = tid; s2 < lim; s2 += 256) {
        int i = s_kept[s2];
        ((float4*)out)[img * POST_NMS + s2] = g_box[img * PRE_NMS + i];
        out[NB * POST_NMS * 4 + img * POST_NMS + s2] = g_prob[img * PRE_NMS + i];
    }
    if (n >= POST_NMS) return;
    // fill with non-kept indices ascending, score = -inf (top_k tie rule)
    unsigned base = 0;
    for (int chunk = 0; chunk < PRE_NMS; chunk += 256) {
        int i = chunk + tid;
        unsigned f = 0u;
        if (i < PRE_NMS) {
            u64 kw = s_km[i >> 6];
            f = ((kw >> (i & 63)) & 1ull) ? 0u : 1u;
        }
        sh[tid] = f;
        __syncthreads();
        for (int off = 1; off < 256; off <<= 1) {
            unsigned vv = (tid >= off) ? sh[tid - off] : 0u;
            __syncthreads();
            sh[tid] += vv;
            __syncthreads();
        }
        unsigned excl = sh[tid] - f;
        int slot = n + (int)(base + excl);
        if (f && slot < POST_NMS) {
            ((float4*)out)[img * POST_NMS + slot] = g_box[img * PRE_NMS + i];
            out[NB * POST_NMS * 4 + img * POST_NMS + slot] =
                __int_as_float(0xff800000);  // -inf
        }
        base += sh[255];
        __syncthreads();
    }
}

// ---------------- host ------------------------------------------------------
extern "C" void kernel_launch(void* const* d_in, const int* in_sizes, int n_in,
                              void* d_out, int out_size) {
    const float* obj     = (const float*)d_in[0];   // (8, 750000)
    const float* deltas  = (const float*)d_in[1];   // (8, 750000, 4)
    const float* anchors = (const float*)d_in[2];   // (750000, 4)
    float* out = (float*)d_out;

    k_zero<<<8, 1024>>>();
    k_hist_c_stage<<<dim3(144, NB), 256>>>(obj);
    k_selects<<<NB, 1024>>>();
    k_fb_hist<<<dim3(144, NB), 256>>>(obj);    // no-op unless fallback
    k_fb_select<<<NB, 256>>>();                // no-op unless fallback

    cudaFuncSetAttribute(k_sortdecode, cudaFuncAttributeMaxDynamicSharedMemorySize,
                         CAND_CAP * (int)sizeof(u64));
    k_sortdecode<<<NB, 1024, CAND_CAP * sizeof(u64)>>>(deltas, anchors);

    k_iou<<<dim3(63, 16, NB), 256>>>();
    k_nmsout<<<NB, 256>>>(out);
}